// round 11
// baseline (speedup 1.0000x reference)
#include <cuda_runtime.h>
#include <cuda_fp16.h>
#include <math.h>

#define NN 50000
#define NN2 100000
#define NE 800000
#define NE2 1600000
#define FIN 64
#define HD 96
#define NG 256
#define SCB 512
#define NSCB2 ((NN2 + SCB - 1) / SCB)   // 196

// ---------------- scratch (device globals; no runtime allocation) -----------
__device__ __align__(16) signed char g_x8[NN2 * FIN];  // input features, int8
__device__ __align__(16) signed char g_h8[NN2 * HD];   // layer outputs, int8
__device__ float g_xsc[NN2];                           // per-row dequant scale for x8
__device__ float g_hsc[NN2];                           // per-row dequant scale for h8
__device__ __align__(16) __half g_aggh[NN2 * HD];      // gather outputs, fp16
__device__ float g_dinv[NN2];
__device__ int   g_deg[NN2];
__device__ int   g_coff[NN2 + 1];
__device__ int   g_cur[NN2];
__device__ __align__(8) int2 g_edge[NE2];              // (local src, norm-bits)
__device__ int   g_bsum[256];
__device__ float g_gate[NN2];

// zero-initialized-per-iteration block (single memset)
struct __align__(16) ZeroBlk {
    float gden[2][NG];
    int   cnt[2][NG];
    float att[2][NG * FIN];
    float pool[2][NG * HD];
};
__device__ ZeroBlk g_z;

// ---------------- helpers ----------------------------------------------------
__device__ __forceinline__ void red4(float* p, float4 v) {
    asm volatile("red.global.add.v4.f32 [%0], {%1,%2,%3,%4};"
                 :: "l"(p), "f"(v.x), "f"(v.y), "f"(v.z), "f"(v.w) : "memory");
}
__device__ __forceinline__ void red2(float* p, float a, float b) {
    asm volatile("red.global.add.v2.f32 [%0], {%1,%2};"
                 :: "l"(p), "f"(a), "f"(b) : "memory");
}

__device__ __forceinline__ void mma16816(float* c, const unsigned* a, unsigned b0, unsigned b1) {
    asm volatile(
        "mma.sync.aligned.m16n8k16.row.col.f32.f16.f16.f32 "
        "{%0,%1,%2,%3}, {%4,%5,%6,%7}, {%8,%9}, {%0,%1,%2,%3};"
        : "+f"(c[0]), "+f"(c[1]), "+f"(c[2]), "+f"(c[3])
        : "r"(a[0]), "r"(a[1]), "r"(a[2]), "r"(a[3]), "r"(b0), "r"(b1));
}

// acc[0..15] += w * (16 int8 in raw)
__device__ __forceinline__ void accq(int4 raw, float w, float* acc) {
    int v[4] = { raw.x, raw.y, raw.z, raw.w };
#pragma unroll
    for (int i = 0; i < 4; i++) {
        int t = v[i];
        acc[4 * i + 0] += w * (float)((signed char)(t));
        acc[4 * i + 1] += w * (float)((signed char)(t >> 8));
        acc[4 * i + 2] += w * (float)((signed char)(t >> 16));
        acc[4 * i + 3] += w * (float)(t >> 24);
    }
}

// ---------------- input quantization: x -> int8 + per-row scale ----------------
__global__ void k_toq8(const float* __restrict__ xp, const float* __restrict__ xd) {
    int lane = threadIdx.x & 31;
    int n = blockIdx.x * (blockDim.x >> 5) + (threadIdx.x >> 5);
    if (n >= NN2) return;
    int side = (n >= NN);
    int nl = n - side * NN;
    const float2* x2 = (const float2*)((side ? xd : xp) + (size_t)nl * FIN);
    float2 v = __ldg(&x2[lane]);
    float m = fmaxf(fabsf(v.x), fabsf(v.y));
#pragma unroll
    for (int o = 16; o > 0; o >>= 1) m = fmaxf(m, __shfl_xor_sync(0xffffffffu, m, o));
    float sinv = (m > 0.f) ? 127.f / m : 0.f;
    int q0 = __float2int_rn(v.x * sinv);
    int q1 = __float2int_rn(v.y * sinv);
    unsigned short u = (unsigned short)((q0 & 0xFF) | ((q1 & 0xFF) << 8));
    *(unsigned short*)&g_x8[(size_t)n * FIN + lane * 2] = u;
    if (lane == 0) g_xsc[n] = m * (1.f / 127.f);
}

// ---------------- degree count (2 edges/thread) --------------------------------
__global__ void k_deg(const int* __restrict__ eip, const int* __restrict__ eid) {
    int t = blockIdx.x * blockDim.x + threadIdx.x;     // NE2/2 threads
    if (t >= NE) return;                               // NE == NE2/2
    int side = (t >= NE / 2);
    int el = (t - side * (NE / 2)) * 2;
    const int* ei = side ? eid : eip;
    int2 d2 = *(const int2*)&ei[NE + el];
    atomicAdd(&g_deg[side * NN + d2.x], 1);
    atomicAdd(&g_deg[side * NN + d2.y], 1);
}

// ---------------- CSR build ----------------------------------------------------
__global__ void k_scan1() {
    __shared__ int s[SCB];
    int i = blockIdx.x * SCB + threadIdx.x;
    s[threadIdx.x] = (i < NN2) ? g_deg[i] : 0;
    __syncthreads();
    for (int o = SCB / 2; o > 0; o >>= 1) {
        if (threadIdx.x < o) s[threadIdx.x] += s[threadIdx.x + o];
        __syncthreads();
    }
    if (threadIdx.x == 0) g_bsum[blockIdx.x] = s[0];
}

__global__ void k_scan3() {
    __shared__ int sb[SCB];
    int t = threadIdx.x;
    sb[t] = (t < blockIdx.x) ? g_bsum[t] : 0;
    __syncthreads();
    for (int o = SCB / 2; o > 0; o >>= 1) {
        if (t < o) sb[t] += sb[t + o];
        __syncthreads();
    }
    int boff = sb[0];
    __syncthreads();
    int i = blockIdx.x * SCB + t;
    int v = (i < NN2) ? g_deg[i] : 0;
    sb[t] = v;
    __syncthreads();
    for (int o = 1; o < SCB; o <<= 1) {
        int a = (t >= o) ? sb[t - o] : 0;
        __syncthreads();
        sb[t] += a;
        __syncthreads();
    }
    if (i < NN2) {
        int off = boff + sb[t] - v;                 // exclusive
        g_coff[i] = off;
        g_cur[i] = off;
        g_dinv[i] = rsqrtf((float)v + 1.0f);
    }
    if (blockIdx.x == NSCB2 - 1 && t == SCB - 1) g_coff[NN2] = boff + sb[t];
}

__global__ void k_csrfill(const int* __restrict__ eip, const int* __restrict__ eid) {
    int t = blockIdx.x * blockDim.x + threadIdx.x;     // NE2/2 threads
    if (t >= NE) return;
    int side = (t >= NE / 2);
    int el = (t - side * (NE / 2)) * 2;
    const int* ei = side ? eid : eip;
    int base = side * NN;
    int2 s2 = *(const int2*)&ei[el];
    int2 d2 = *(const int2*)&ei[NE + el];
    {
        float norm = g_dinv[base + s2.x] * g_dinv[base + d2.x];
        int slot = atomicAdd(&g_cur[base + d2.x], 1);
        g_edge[slot] = make_int2(s2.x, __float_as_int(norm));
    }
    {
        float norm = g_dinv[base + s2.y] * g_dinv[base + d2.y];
        int slot = atomicAdd(&g_cur[base + d2.y], 1);
        g_edge[slot] = make_int2(s2.y, __float_as_int(norm));
    }
}

// ---------------- attention gate (both sides) ----------------------------------
__global__ void k_gate(const float* __restrict__ xp, const float* __restrict__ xd,
                       const int* __restrict__ bp, const int* __restrict__ bd,
                       const float* __restrict__ gW1, const float* __restrict__ gb1,
                       const float* __restrict__ gW2, const float* __restrict__ gb2) {
    int lane = threadIdx.x & 31;
    int n = blockIdx.x * (blockDim.x >> 5) + (threadIdx.x >> 5);
    if (n >= NN2) return;
    int side = (n >= NN);
    int nl = n - side * NN;
    const float* x = side ? xd : xp;
    const int* batch = side ? bd : bp;
    float xa = x[nl * FIN + lane];
    float xb = x[nl * FIN + 32 + lane];
    float acc0 = gb1[lane];
    float acc1 = gb1[lane + 32];
#pragma unroll
    for (int k = 0; k < FIN; k++) {
        float xk = __shfl_sync(0xffffffffu, (k < 32) ? xa : xb, k & 31);
        acc0 += xk * gW1[k * FIN + lane];
        acc1 += xk * gW1[k * FIN + lane + 32];
    }
    float h = fmaxf(acc0, 0.f) * gW2[lane] + fmaxf(acc1, 0.f) * gW2[lane + 32];
#pragma unroll
    for (int o = 16; o > 0; o >>= 1) h += __shfl_down_sync(0xffffffffu, h, o);
    if (lane == 0) {
        float e = expf(h + gb2[0]);        // gates tiny: no max-shift needed
        g_gate[n] = e;
        int b = batch[nl];
        atomicAdd(&g_z.gden[side][b], e);
        atomicAdd(&g_z.cnt[side][b], 1);
    }
}

__global__ void k_attpool(const float* __restrict__ xp, const float* __restrict__ xd,
                          const int* __restrict__ bp, const int* __restrict__ bd) {
    int idx = blockIdx.x * blockDim.x + threadIdx.x;     // NN2 * 16
    if (idx >= NN2 * (FIN / 4)) return;
    int n = idx >> 4, j = idx & 15;
    int side = (n >= NN);
    int nl = n - side * NN;
    int b = side ? bd[nl] : bp[nl];
    float alpha = g_gate[n] / g_z.gden[side][b];
    const float4* x4 = side ? (const float4*)xd : (const float4*)xp;
    float4 v = __ldg(&x4[nl * (FIN / 4) + j]);
    v.x *= alpha; v.y *= alpha; v.z *= alpha; v.w *= alpha;
    red4(&g_z.att[side][b * FIN + j * 4], v);
}

// ---------------- int8 CSR gather -> fp16 agg ----------------------------------
// agg[n] = dinv^2*sc[n]*q[n] + sum norm*sc[src]*q[src]; fp32 accum, fp16 store.
// f8: int8 rows of K16*16 bytes; sc: per-row dequant scale.
__global__ void k_gatherq(const int4* __restrict__ f8, const float* __restrict__ sc,
                          int K16) {
    int idx = blockIdx.x * blockDim.x + threadIdx.x;
    if (idx >= NN2 * K16) return;
    int n = idx / K16, j = idx - n * K16;
    int base = (n >= NN) ? NN : 0;
    float dv = g_dinv[n];
    float acc[16];
#pragma unroll
    for (int i = 0; i < 16; i++) acc[i] = 0.f;
    accq(__ldg(&f8[(size_t)n * K16 + j]), dv * dv * __ldg(&sc[n]), acc);
    int p = __ldg(&g_coff[n]);
    int end = __ldg(&g_coff[n + 1]);
    for (; p + 3 < end; p += 4) {
        int2 e0 = __ldg(&g_edge[p]);
        int2 e1 = __ldg(&g_edge[p + 1]);
        int2 e2 = __ldg(&g_edge[p + 2]);
        int2 e3 = __ldg(&g_edge[p + 3]);
        int4 a0 = __ldg(&f8[(size_t)(base + e0.x) * K16 + j]);
        int4 a1 = __ldg(&f8[(size_t)(base + e1.x) * K16 + j]);
        int4 a2 = __ldg(&f8[(size_t)(base + e2.x) * K16 + j]);
        int4 a3 = __ldg(&f8[(size_t)(base + e3.x) * K16 + j]);
        float w0 = __int_as_float(e0.y) * __ldg(&sc[base + e0.x]);
        float w1 = __int_as_float(e1.y) * __ldg(&sc[base + e1.x]);
        float w2 = __int_as_float(e2.y) * __ldg(&sc[base + e2.x]);
        float w3 = __int_as_float(e3.y) * __ldg(&sc[base + e3.x]);
        accq(a0, w0, acc);
        accq(a1, w1, acc);
        accq(a2, w2, acc);
        accq(a3, w3, acc);
    }
    for (; p < end; p++) {
        int2 e0 = __ldg(&g_edge[p]);
        float w0 = __int_as_float(e0.y) * __ldg(&sc[base + e0.x]);
        accq(__ldg(&f8[(size_t)(base + e0.x) * K16 + j]), w0, acc);
    }
    // store 16 halves = 2 x int4
    int4 o0, o1;
    __half2 h;
    h = __floats2half2_rn(acc[0], acc[1]);   o0.x = *(int*)&h;
    h = __floats2half2_rn(acc[2], acc[3]);   o0.y = *(int*)&h;
    h = __floats2half2_rn(acc[4], acc[5]);   o0.z = *(int*)&h;
    h = __floats2half2_rn(acc[6], acc[7]);   o0.w = *(int*)&h;
    h = __floats2half2_rn(acc[8], acc[9]);   o1.x = *(int*)&h;
    h = __floats2half2_rn(acc[10], acc[11]); o1.y = *(int*)&h;
    h = __floats2half2_rn(acc[12], acc[13]); o1.z = *(int*)&h;
    h = __floats2half2_rn(acc[14], acc[15]); o1.w = *(int*)&h;
    ((int4*)g_aggh)[idx * 2]     = o0;
    ((int4*)g_aggh)[idx * 2 + 1] = o1;
}

// ---------------- HMMA GEMM: out[rows,96] = aggh[rows,K] @ W[K,96] + b ----------
// outQ: relu + per-row int8 quantization -> g_h8/g_hsc.  fusePool: mean-pool sums.
__global__ void __launch_bounds__(256) k_gemm_mma(
        const float* __restrict__ Wp, const float* __restrict__ Wd,
        const float* __restrict__ bp, const float* __restrict__ bd,
        int K, int outQ, int fusePool,
        const int* __restrict__ batch_p, const int* __restrict__ batch_d) {
    extern __shared__ __half sm[];
    const int KS = K + 8;
    __half* As  = sm;                     // 128 x KS
    __half* Bhi = As + 128 * KS;          // 96 x KS  ([n][k])
    __half* Blo = Bhi + 96 * KS;
    const int side = blockIdx.x & 1;
    const int tile = blockIdx.x >> 1;
    const int rowBase = tile * 128;
    const float* W = side ? Wd : Wp;
    const float* bias = side ? bd : bp;
    const int* batch = side ? batch_d : batch_p;
    const int tid = threadIdx.x;
    const int K8 = K >> 3;

    for (int i = tid; i < K * HD; i += 256) {
        int k = i / HD, n = i - k * HD;
        float w = __ldg(&W[i]);
        __half hi = __float2half_rn(w);
        __half lo = __float2half_rn(w - __half2float(hi));
        Bhi[n * KS + k] = hi;
        Blo[n * KS + k] = lo;
    }
    const int4* Ah = (const int4*)g_aggh;
    for (int i = tid; i < 128 * K8; i += 256) {
        int r = i / K8, j = i - r * K8;
        int row = rowBase + r;
        int4 v = make_int4(0, 0, 0, 0);
        if (row < NN) v = __ldg(&Ah[(size_t)(side * NN + row) * K8 + j]);
        *(int4*)&As[r * KS + j * 8] = v;
    }
    __syncthreads();

    const int warp = tid >> 5;
    const int lane = tid & 31;
    const int g = lane >> 2;
    const int tg = lane & 3;
    const int warpRow = warp * 16;

    float c[12][4];
#pragma unroll
    for (int nt = 0; nt < 12; nt++)
#pragma unroll
        for (int q = 0; q < 4; q++) c[nt][q] = 0.f;

    const int nk = K >> 4;
    for (int ks = 0; ks < nk; ks++) {
        unsigned a[4];
        const __half* arow0 = &As[(warpRow + g) * KS + ks * 16 + tg * 2];
        const __half* arow1 = arow0 + 8 * KS;
        a[0] = *(const unsigned*)arow0;
        a[1] = *(const unsigned*)arow1;
        a[2] = *(const unsigned*)(arow0 + 8);
        a[3] = *(const unsigned*)(arow1 + 8);
#pragma unroll
        for (int nt = 0; nt < 12; nt++) {
            const __half* brow = &Bhi[(nt * 8 + g) * KS + ks * 16 + tg * 2];
            unsigned b0 = *(const unsigned*)brow;
            unsigned b1 = *(const unsigned*)(brow + 8);
            mma16816(c[nt], a, b0, b1);
            const __half* brl = &Blo[(nt * 8 + g) * KS + ks * 16 + tg * 2];
            unsigned l0 = *(const unsigned*)brl;
            unsigned l1 = *(const unsigned*)(brl + 8);
            mma16816(c[nt], a, l0, l1);
        }
    }

    int row0 = rowBase + warpRow + g;
    int row1 = row0 + 8;

    if (outQ) {
        // relu in-place, then per-row max across nt and the 4-lane tg group
        float m0 = 0.f, m1 = 0.f;
#pragma unroll
        for (int nt = 0; nt < 12; nt++) {
            int col = nt * 8 + tg * 2;
            float bx = __ldg(&bias[col]);
            float by = __ldg(&bias[col + 1]);
            c[nt][0] = fmaxf(c[nt][0] + bx, 0.f);
            c[nt][1] = fmaxf(c[nt][1] + by, 0.f);
            c[nt][2] = fmaxf(c[nt][2] + bx, 0.f);
            c[nt][3] = fmaxf(c[nt][3] + by, 0.f);
            m0 = fmaxf(m0, fmaxf(c[nt][0], c[nt][1]));
            m1 = fmaxf(m1, fmaxf(c[nt][2], c[nt][3]));
        }
        m0 = fmaxf(m0, __shfl_xor_sync(0xffffffffu, m0, 1));
        m0 = fmaxf(m0, __shfl_xor_sync(0xffffffffu, m0, 2));
        m1 = fmaxf(m1, __shfl_xor_sync(0xffffffffu, m1, 1));
        m1 = fmaxf(m1, __shfl_xor_sync(0xffffffffu, m1, 2));
        float si0 = (m0 > 0.f) ? 127.f / m0 : 0.f;
        float si1 = (m1 > 0.f) ? 127.f / m1 : 0.f;
        size_t grow0 = (size_t)side * NN + row0;
        size_t grow1 = (size_t)side * NN + row1;
        if (tg == 0) {
            if (row0 < NN) g_hsc[grow0] = m0 * (1.f / 127.f);
            if (row1 < NN) g_hsc[grow1] = m1 * (1.f / 127.f);
        }
#pragma unroll
        for (int nt = 0; nt < 12; nt++) {
            int col = nt * 8 + tg * 2;
            if (row0 < NN) {
                int q0 = __float2int_rn(c[nt][0] * si0);
                int q1 = __float2int_rn(c[nt][1] * si0);
                *(unsigned short*)&g_h8[grow0 * HD + col] =
                    (unsigned short)((q0 & 0xFF) | ((q1 & 0xFF) << 8));
            }
            if (row1 < NN) {
                int q0 = __float2int_rn(c[nt][2] * si1);
                int q1 = __float2int_rn(c[nt][3] * si1);
                *(unsigned short*)&g_h8[grow1 * HD + col] =
                    (unsigned short)((q0 & 0xFF) | ((q1 & 0xFF) << 8));
            }
        }
    } else {
#pragma unroll
        for (int nt = 0; nt < 12; nt++) {
            int col = nt * 8 + tg * 2;
            float bx = __ldg(&bias[col]);
            float by = __ldg(&bias[col + 1]);
            float v00 = c[nt][0] + bx, v01 = c[nt][1] + by;
            float v10 = c[nt][2] + bx, v11 = c[nt][3] + by;
            if (row0 < NN) red2(&g_z.pool[side][batch[row0] * HD + col], v00, v01);
            if (row1 < NN) red2(&g_z.pool[side][batch[row1] * HD + col], v10, v11);
        }
    }
}

// ---------------- final MLP ---------------------------------------------------
__global__ void k_final(const float* __restrict__ lW0, const float* __restrict__ lb0,
                        const float* __restrict__ lW1, const float* __restrict__ lb1,
                        float* __restrict__ out) {
    int g = blockIdx.x;
    int j = threadIdx.x;                                 // 96 threads
    __shared__ float cat[2 * HD + 2 * FIN];              // 320
    __shared__ float red[HD];
    for (int i = j; i < 2 * HD + 2 * FIN; i += HD) {
        float v;
        if (i < HD)            v = g_z.pool[0][g * HD + i] / fmaxf((float)g_z.cnt[0][g], 1.f);
        else if (i < 2 * HD)   v = g_z.pool[1][g * HD + (i - HD)] / fmaxf((float)g_z.cnt[1][g], 1.f);
        else if (i < 2 * HD + FIN) v = g_z.att[0][g * FIN + (i - 2 * HD)];
        else                   v = g_z.att[1][g * FIN + (i - 2 * HD - FIN)];
        cat[i] = v;
    }
    __syncthreads();
    float acc = lb0[j];
#pragma unroll 8
    for (int i = 0; i < 2 * HD + 2 * FIN; i++)
        acc += cat[i] * lW0[i * HD + j];
    red[j] = fmaxf(acc, 0.f) * lW1[j];
    __syncthreads();
    if (j == 0) {
        float s = lb1[0];
        for (int t = 0; t < HD; t++) s += red[t];
        out[g] = s;
    }
}

// ---------------- host launcher ----------------------------------------------
extern "C" void kernel_launch(void* const* d_in, const int* in_sizes, int n_in,
                              void* d_out, int out_size) {
    const float* xp  = (const float*)d_in[0];
    const float* xd  = (const float*)d_in[1];
    const int*   eip = (const int*)d_in[4];
    const int*   eid = (const int*)d_in[5];
    const int*   bp  = (const int*)d_in[6];
    const int*   bd  = (const int*)d_in[7];
    const float* Wp0 = (const float*)d_in[8],  *bp0 = (const float*)d_in[9];
    const float* Wp1 = (const float*)d_in[10], *bp1 = (const float*)d_in[11];
    const float* Wp2 = (const float*)d_in[12], *bp2 = (const float*)d_in[13];
    const float* Wd0 = (const float*)d_in[14], *bd0 = (const float*)d_in[15];
    const float* Wd1 = (const float*)d_in[16], *bd1 = (const float*)d_in[17];
    const float* Wd2 = (const float*)d_in[18], *bd2 = (const float*)d_in[19];
    const float* gW1 = (const float*)d_in[20], *gb1 = (const float*)d_in[21];
    const float* gW2 = (const float*)d_in[22], *gb2 = (const float*)d_in[23];
    const float* lW0 = (const float*)d_in[24], *lb0 = (const float*)d_in[25];
    const float* lW1 = (const float*)d_in[26], *lb1 = (const float*)d_in[27];

    const int TB = 256;
    const int GB_EH = (NE + TB - 1) / TB;            // 2-edges/thread grids
    const int GB_C16 = (NN2 * 16 + TB - 1) / TB;
    const int GB_Q4  = (NN2 * 4 + TB - 1) / TB;      // layer-0 gather (K16=4)
    const int GB_Q6  = (NN2 * 6 + TB - 1) / TB;      // layer-1/2 gather (K16=6)
    const int GEMM_GRID = 782;                       // 391 tiles x 2 sides
    const int SMEM96 = (128 + 96 + 96) * (96 + 8) * 2;   // 66560 B
    const int SMEM64 = (128 + 96 + 96) * (64 + 8) * 2;   // 46080 B

    static cudaStream_t s2 = nullptr;
    static cudaEvent_t ev1 = nullptr, evT = nullptr, ev2 = nullptr;
    static int inited = 0;
    if (!inited) {
        cudaFuncSetAttribute(k_gemm_mma, cudaFuncAttributeMaxDynamicSharedMemorySize, SMEM96);
        cudaStreamCreateWithFlags(&s2, cudaStreamNonBlocking);
        cudaEventCreateWithFlags(&ev1, cudaEventDisableTiming);
        cudaEventCreateWithFlags(&evT, cudaEventDisableTiming);
        cudaEventCreateWithFlags(&ev2, cudaEventDisableTiming);
        inited = 1;
    }

    void* x8_dev = nullptr;  cudaGetSymbolAddress(&x8_dev, g_x8);
    void* h8_dev = nullptr;  cudaGetSymbolAddress(&h8_dev, g_h8);
    void* xsc_dev = nullptr; cudaGetSymbolAddress(&xsc_dev, g_xsc);
    void* hsc_dev = nullptr; cudaGetSymbolAddress(&hsc_dev, g_hsc);
    void* deg_dev = nullptr; cudaGetSymbolAddress(&deg_dev, g_deg);
    void* z_dev = nullptr;   cudaGetSymbolAddress(&z_dev, g_z);

    // ---- fork ----
    cudaEventRecord(ev1, 0);
    cudaStreamWaitEvent(s2, ev1, 0);

    // stream B: zero-init, quantize x (needed by gathers), then gate+attpool
    cudaMemsetAsync(z_dev, 0, sizeof(ZeroBlk), s2);
    k_toq8<<<(NN2 + 7) / 8, 256, 0, s2>>>(xp, xd);
    cudaEventRecord(evT, s2);                 // gathers need only this from B
    k_gate<<<(NN2 + 7) / 8, 256, 0, s2>>>(xp, xd, bp, bd, gW1, gb1, gW2, gb2);
    k_attpool<<<GB_C16, TB, 0, s2>>>(xp, xd, bp, bd);
    cudaEventRecord(ev2, s2);                 // k_final needs this

    // stream A (default): CSR build
    cudaMemsetAsync(deg_dev, 0, NN2 * sizeof(int), 0);
    k_deg<<<GB_EH, TB>>>(eip, eid);
    k_scan1<<<NSCB2, SCB>>>();
    k_scan3<<<NSCB2, SCB>>>();
    k_csrfill<<<GB_EH, TB>>>(eip, eid);

    // join #1: gathers need x quantized; attpool continues concurrently on B
    cudaStreamWaitEvent(0, evT, 0);

    // layer 0: gather x8 (K=64) -> aggh; HMMA GEMM 64->96 -> int8 h8 (+relu)
    k_gatherq<<<GB_Q4, TB>>>((const int4*)x8_dev, (const float*)xsc_dev, 4);
    k_gemm_mma<<<GEMM_GRID, 256, SMEM64>>>(Wp0, Wd0, bp0, bd0, 64, 1, 0, bp, bd);
    // layer 1
    k_gatherq<<<GB_Q6, TB>>>((const int4*)h8_dev, (const float*)hsc_dev, 6);
    k_gemm_mma<<<GEMM_GRID, 256, SMEM96>>>(Wp1, Wd1, bp1, bd1, 96, 1, 0, bp, bd);
    // layer 2 (+ fused mean-pool sums, fp32)
    k_gatherq<<<GB_Q6, TB>>>((const int4*)h8_dev, (const float*)hsc_dev, 6);
    k_gemm_mma<<<GEMM_GRID, 256, SMEM96>>>(Wp2, Wd2, bp2, bd2, 96, 0, 1, bp, bd);

    // join #2: k_final reads g_z.att / g_z.gden written on stream B
    cudaStreamWaitEvent(0, ev2, 0);
    k_final<<<NG, HD>>>(lW0, lb0, lW1, lb1, (float*)d_out);
}

// round 12
// speedup vs baseline: 1.5537x; 1.5537x over previous
#include <cuda_runtime.h>
#include <cuda_fp16.h>
#include <math.h>

#define NN 50000
#define NN2 100000
#define NE 800000
#define NE2 1600000
#define FIN 64
#define HD 96
#define NG 256
#define SCB 512
#define NSCB2 ((NN2 + SCB - 1) / SCB)   // 196

// ---------------- scratch (device globals; no runtime allocation) -----------
__device__ __align__(16) __half g_hh[NN2 * HD];   // layer outputs, fp16
__device__ __align__(16) __half g_xh[NN2 * FIN];  // input features, fp16
__device__ __align__(16) __half g_aggh[NN2 * HD]; // gather outputs, fp16
__device__ float g_dinv[NN2];
__device__ int   g_deg[NN2];
__device__ int   g_coff[NN2 + 1];
__device__ int   g_cur[NN2];
__device__ __align__(8) int2 g_edge[NE2];         // (local src, norm-bits)
__device__ int   g_bsum[256];
__device__ float g_gate[NN2];

// zero-initialized-per-iteration block (single memset)
struct __align__(16) ZeroBlk {
    float gden[2][NG];
    int   cnt[2][NG];
    float att[2][NG * FIN];
    float pool[2][NG * HD];
};
__device__ ZeroBlk g_z;

// ---------------- helpers ----------------------------------------------------
__device__ __forceinline__ void red4(float* p, float4 v) {
    asm volatile("red.global.add.v4.f32 [%0], {%1,%2,%3,%4};"
                 :: "l"(p), "f"(v.x), "f"(v.y), "f"(v.z), "f"(v.w) : "memory");
}
__device__ __forceinline__ void red2(float* p, float a, float b) {
    asm volatile("red.global.add.v2.f32 [%0], {%1,%2};"
                 :: "l"(p), "f"(a), "f"(b) : "memory");
}

__device__ __forceinline__ void mma16816(float* c, const unsigned* a, unsigned b0, unsigned b1) {
    asm volatile(
        "mma.sync.aligned.m16n8k16.row.col.f32.f16.f16.f32 "
        "{%0,%1,%2,%3}, {%4,%5,%6,%7}, {%8,%9}, {%0,%1,%2,%3};"
        : "+f"(c[0]), "+f"(c[1]), "+f"(c[2]), "+f"(c[3])
        : "r"(a[0]), "r"(a[1]), "r"(a[2]), "r"(a[3]), "r"(b0), "r"(b1));
}

// acc[0..7] += w * (8 halves in raw)
__device__ __forceinline__ void fma8(int4 raw, float w, float* acc) {
    __half2* h = reinterpret_cast<__half2*>(&raw);
#pragma unroll
    for (int i = 0; i < 4; i++) {
        float2 f = __half22float2(h[i]);
        acc[2 * i]     += w * f.x;
        acc[2 * i + 1] += w * f.y;
    }
}

// ---------------- input conversion ---------------------------------------------
__global__ void k_tohalf(const float4* __restrict__ xp, const float4* __restrict__ xd) {
    int idx = blockIdx.x * blockDim.x + threadIdx.x;      // NN2 * 16
    if (idx >= NN2 * 16) return;
    int n = idx >> 4;
    int side = (n >= NN);
    int nl = n - side * NN;
    float4 v = __ldg(&(side ? xd : xp)[nl * 16 + (idx & 15)]);
    __half2 h0 = __floats2half2_rn(v.x, v.y);
    __half2 h1 = __floats2half2_rn(v.z, v.w);
    uint2 u;
    u.x = *(unsigned*)&h0; u.y = *(unsigned*)&h1;
    ((uint2*)g_xh)[idx] = u;
}

__global__ void k_deg(const int* __restrict__ eip, const int* __restrict__ eid) {
    int e = blockIdx.x * blockDim.x + threadIdx.x;
    if (e >= NE2) return;
    int side = (e >= NE);
    int el = e - side * NE;
    const int* ei = side ? eid : eip;
    atomicAdd(&g_deg[side * NN + ei[NE + el]], 1);
}

// ---------------- CSR build ----------------------------------------------------
__global__ void k_scan1() {
    __shared__ int s[SCB];
    int i = blockIdx.x * SCB + threadIdx.x;
    s[threadIdx.x] = (i < NN2) ? g_deg[i] : 0;
    __syncthreads();
    for (int o = SCB / 2; o > 0; o >>= 1) {
        if (threadIdx.x < o) s[threadIdx.x] += s[threadIdx.x + o];
        __syncthreads();
    }
    if (threadIdx.x == 0) g_bsum[blockIdx.x] = s[0];
}

// scan3: per-block offset computed in-block from g_bsum
__global__ void k_scan3() {
    __shared__ int sb[SCB];
    int t = threadIdx.x;
    sb[t] = (t < blockIdx.x) ? g_bsum[t] : 0;       // blockIdx.x < 196 <= SCB
    __syncthreads();
    for (int o = SCB / 2; o > 0; o >>= 1) {
        if (t < o) sb[t] += sb[t + o];
        __syncthreads();
    }
    int boff = sb[0];
    __syncthreads();
    int i = blockIdx.x * SCB + t;
    int v = (i < NN2) ? g_deg[i] : 0;
    sb[t] = v;
    __syncthreads();
    for (int o = 1; o < SCB; o <<= 1) {
        int a = (t >= o) ? sb[t - o] : 0;
        __syncthreads();
        sb[t] += a;
        __syncthreads();
    }
    if (i < NN2) {
        int off = boff + sb[t] - v;                 // exclusive
        g_coff[i] = off;
        g_cur[i] = off;
        g_dinv[i] = rsqrtf((float)v + 1.0f);
    }
    if (blockIdx.x == NSCB2 - 1 && t == SCB - 1) g_coff[NN2] = boff + sb[t];
}

__global__ void k_csrfill(const int* __restrict__ eip, const int* __restrict__ eid) {
    int e = blockIdx.x * blockDim.x + threadIdx.x;
    if (e >= NE2) return;
    int side = (e >= NE);
    int el = e - side * NE;
    const int* ei = side ? eid : eip;
    int s = ei[el], d = ei[NE + el];
    int base = side * NN;
    float norm = g_dinv[base + s] * g_dinv[base + d];
    int slot = atomicAdd(&g_cur[base + d], 1);
    g_edge[slot] = make_int2(s, __float_as_int(norm));
}

// ---------------- attention gate (both sides) ----------------------------------
__global__ void k_gate(const float* __restrict__ xp, const float* __restrict__ xd,
                       const int* __restrict__ bp, const int* __restrict__ bd,
                       const float* __restrict__ gW1, const float* __restrict__ gb1,
                       const float* __restrict__ gW2, const float* __restrict__ gb2) {
    int lane = threadIdx.x & 31;
    int n = blockIdx.x * (blockDim.x >> 5) + (threadIdx.x >> 5);
    if (n >= NN2) return;
    int side = (n >= NN);
    int nl = n - side * NN;
    const float* x = side ? xd : xp;
    const int* batch = side ? bd : bp;
    float xa = x[nl * FIN + lane];
    float xb = x[nl * FIN + 32 + lane];
    float acc0 = gb1[lane];
    float acc1 = gb1[lane + 32];
#pragma unroll
    for (int k = 0; k < FIN; k++) {
        float xk = __shfl_sync(0xffffffffu, (k < 32) ? xa : xb, k & 31);
        acc0 += xk * gW1[k * FIN + lane];
        acc1 += xk * gW1[k * FIN + lane + 32];
    }
    float h = fmaxf(acc0, 0.f) * gW2[lane] + fmaxf(acc1, 0.f) * gW2[lane + 32];
#pragma unroll
    for (int o = 16; o > 0; o >>= 1) h += __shfl_down_sync(0xffffffffu, h, o);
    if (lane == 0) {
        float e = expf(h + gb2[0]);        // gates tiny: no max-shift needed
        g_gate[n] = e;
        int b = batch[nl];
        atomicAdd(&g_z.gden[side][b], e);
        atomicAdd(&g_z.cnt[side][b], 1);
    }
}

__global__ void k_attpool(const float* __restrict__ xp, const float* __restrict__ xd,
                          const int* __restrict__ bp, const int* __restrict__ bd) {
    int idx = blockIdx.x * blockDim.x + threadIdx.x;     // NN2 * 16
    if (idx >= NN2 * (FIN / 4)) return;
    int n = idx >> 4, j = idx & 15;
    int side = (n >= NN);
    int nl = n - side * NN;
    int b = side ? bd[nl] : bp[nl];
    float alpha = g_gate[n] / g_z.gden[side][b];
    const float4* x4 = side ? (const float4*)xd : (const float4*)xp;
    float4 v = __ldg(&x4[nl * (FIN / 4) + j]);
    v.x *= alpha; v.y *= alpha; v.z *= alpha; v.w *= alpha;
    red4(&g_z.att[side][b * FIN + j * 4], v);
}

// ---------------- fp16 CSR gather -> fp16 agg (8-wide edge unroll) -------------
__global__ void k_gatherh(const int4* __restrict__ f16, int K8) {
    int idx = blockIdx.x * blockDim.x + threadIdx.x;
    if (idx >= NN2 * K8) return;
    int n = idx / K8, j = idx - n * K8;
    int base = (n >= NN) ? NN : 0;
    float dv = g_dinv[n];
    float acc[8] = {0.f, 0.f, 0.f, 0.f, 0.f, 0.f, 0.f, 0.f};
    fma8(__ldg(&f16[(size_t)n * K8 + j]), dv * dv, acc);
    int p = __ldg(&g_coff[n]);
    int end = __ldg(&g_coff[n + 1]);
    for (; p + 7 < end; p += 8) {
        int2 e0 = __ldg(&g_edge[p]);
        int2 e1 = __ldg(&g_edge[p + 1]);
        int2 e2 = __ldg(&g_edge[p + 2]);
        int2 e3 = __ldg(&g_edge[p + 3]);
        int2 e4 = __ldg(&g_edge[p + 4]);
        int2 e5 = __ldg(&g_edge[p + 5]);
        int2 e6 = __ldg(&g_edge[p + 6]);
        int2 e7 = __ldg(&g_edge[p + 7]);
        int4 a0 = __ldg(&f16[(size_t)(base + e0.x) * K8 + j]);
        int4 a1 = __ldg(&f16[(size_t)(base + e1.x) * K8 + j]);
        int4 a2 = __ldg(&f16[(size_t)(base + e2.x) * K8 + j]);
        int4 a3 = __ldg(&f16[(size_t)(base + e3.x) * K8 + j]);
        int4 a4 = __ldg(&f16[(size_t)(base + e4.x) * K8 + j]);
        int4 a5 = __ldg(&f16[(size_t)(base + e5.x) * K8 + j]);
        int4 a6 = __ldg(&f16[(size_t)(base + e6.x) * K8 + j]);
        int4 a7 = __ldg(&f16[(size_t)(base + e7.x) * K8 + j]);
        fma8(a0, __int_as_float(e0.y), acc);
        fma8(a1, __int_as_float(e1.y), acc);
        fma8(a2, __int_as_float(e2.y), acc);
        fma8(a3, __int_as_float(e3.y), acc);
        fma8(a4, __int_as_float(e4.y), acc);
        fma8(a5, __int_as_float(e5.y), acc);
        fma8(a6, __int_as_float(e6.y), acc);
        fma8(a7, __int_as_float(e7.y), acc);
    }
    for (; p + 1 < end; p += 2) {
        int2 e0 = __ldg(&g_edge[p]);
        int2 e1 = __ldg(&g_edge[p + 1]);
        int4 a0 = __ldg(&f16[(size_t)(base + e0.x) * K8 + j]);
        int4 a1 = __ldg(&f16[(size_t)(base + e1.x) * K8 + j]);
        fma8(a0, __int_as_float(e0.y), acc);
        fma8(a1, __int_as_float(e1.y), acc);
    }
    if (p < end) {
        int2 e0 = __ldg(&g_edge[p]);
        fma8(__ldg(&f16[(size_t)(base + e0.x) * K8 + j]), __int_as_float(e0.y), acc);
    }
    __half2 h0 = __floats2half2_rn(acc[0], acc[1]);
    __half2 h1 = __floats2half2_rn(acc[2], acc[3]);
    __half2 h2 = __floats2half2_rn(acc[4], acc[5]);
    __half2 h3 = __floats2half2_rn(acc[6], acc[7]);
    int4 o;
    o.x = *(int*)&h0; o.y = *(int*)&h1; o.z = *(int*)&h2; o.w = *(int*)&h3;
    ((int4*)g_aggh)[idx] = o;
}

// ---------------- HMMA GEMM: out[rows,96] = aggh[rows,K] @ W[K,96] + b ----------
__global__ void __launch_bounds__(256) k_gemm_mma(
        const float* __restrict__ Wp, const float* __restrict__ Wd,
        const float* __restrict__ bp, const float* __restrict__ bd,
        int K, int reluOut, int fusePool,
        const int* __restrict__ batch_p, const int* __restrict__ batch_d) {
    extern __shared__ __half sm[];
    const int KS = K + 8;
    __half* As  = sm;                     // 128 x KS
    __half* Bhi = As + 128 * KS;          // 96 x KS  ([n][k])
    __half* Blo = Bhi + 96 * KS;
    const int side = blockIdx.x & 1;
    const int tile = blockIdx.x >> 1;
    const int rowBase = tile * 128;
    const float* W = side ? Wd : Wp;
    const float* bias = side ? bd : bp;
    const int* batch = side ? batch_d : batch_p;
    const int tid = threadIdx.x;
    const int K8 = K >> 3;

    for (int i = tid; i < K * HD; i += 256) {
        int k = i / HD, n = i - k * HD;
        float w = __ldg(&W[i]);
        __half hi = __float2half_rn(w);
        __half lo = __float2half_rn(w - __half2float(hi));
        Bhi[n * KS + k] = hi;
        Blo[n * KS + k] = lo;
    }
    const int4* Ah = (const int4*)g_aggh;
    for (int i = tid; i < 128 * K8; i += 256) {
        int r = i / K8, j = i - r * K8;
        int row = rowBase + r;
        int4 v = make_int4(0, 0, 0, 0);
        if (row < NN) v = __ldg(&Ah[(size_t)(side * NN + row) * K8 + j]);
        *(int4*)&As[r * KS + j * 8] = v;
    }
    __syncthreads();

    const int warp = tid >> 5;
    const int lane = tid & 31;
    const int g = lane >> 2;
    const int tg = lane & 3;
    const int warpRow = warp * 16;

    float c[12][4];
#pragma unroll
    for (int nt = 0; nt < 12; nt++)
#pragma unroll
        for (int q = 0; q < 4; q++) c[nt][q] = 0.f;

    const int nk = K >> 4;
    for (int ks = 0; ks < nk; ks++) {
        unsigned a[4];
        const __half* arow0 = &As[(warpRow + g) * KS + ks * 16 + tg * 2];
        const __half* arow1 = arow0 + 8 * KS;
        a[0] = *(const unsigned*)arow0;
        a[1] = *(const unsigned*)arow1;
        a[2] = *(const unsigned*)(arow0 + 8);
        a[3] = *(const unsigned*)(arow1 + 8);
#pragma unroll
        for (int nt = 0; nt < 12; nt++) {
            const __half* brow = &Bhi[(nt * 8 + g) * KS + ks * 16 + tg * 2];
            unsigned b0 = *(const unsigned*)brow;
            unsigned b1 = *(const unsigned*)(brow + 8);
            mma16816(c[nt], a, b0, b1);
            const __half* brl = &Blo[(nt * 8 + g) * KS + ks * 16 + tg * 2];
            unsigned l0 = *(const unsigned*)brl;
            unsigned l1 = *(const unsigned*)(brl + 8);
            mma16816(c[nt], a, l0, l1);
        }
    }

    int row0 = rowBase + warpRow + g;
    int row1 = row0 + 8;
#pragma unroll
    for (int nt = 0; nt < 12; nt++) {
        int col = nt * 8 + tg * 2;
        float bx = __ldg(&bias[col]);
        float by = __ldg(&bias[col + 1]);
        float v00 = c[nt][0] + bx, v01 = c[nt][1] + by;
        float v10 = c[nt][2] + bx, v11 = c[nt][3] + by;
        if (!fusePool) {
            if (reluOut) {
                v00 = fmaxf(v00, 0.f); v01 = fmaxf(v01, 0.f);
                v10 = fmaxf(v10, 0.f); v11 = fmaxf(v11, 0.f);
            }
            if (row0 < NN) {
                __half2 h = __floats2half2_rn(v00, v01);
                *(unsigned*)&g_hh[(size_t)(side * NN + row0) * HD + col] = *(unsigned*)&h;
            }
            if (row1 < NN) {
                __half2 h = __floats2half2_rn(v10, v11);
                *(unsigned*)&g_hh[(size_t)(side * NN + row1) * HD + col] = *(unsigned*)&h;
            }
        } else {
            if (row0 < NN) red2(&g_z.pool[side][batch[row0] * HD + col], v00, v01);
            if (row1 < NN) red2(&g_z.pool[side][batch[row1] * HD + col], v10, v11);
        }
    }
}

// ---------------- final MLP ---------------------------------------------------
__global__ void k_final(const float* __restrict__ lW0, const float* __restrict__ lb0,
                        const float* __restrict__ lW1, const float* __restrict__ lb1,
                        float* __restrict__ out) {
    int g = blockIdx.x;
    int j = threadIdx.x;                                 // 96 threads
    __shared__ float cat[2 * HD + 2 * FIN];              // 320
    __shared__ float red[HD];
    for (int i = j; i < 2 * HD + 2 * FIN; i += HD) {
        float v;
        if (i < HD)            v = g_z.pool[0][g * HD + i] / fmaxf((float)g_z.cnt[0][g], 1.f);
        else if (i < 2 * HD)   v = g_z.pool[1][g * HD + (i - HD)] / fmaxf((float)g_z.cnt[1][g], 1.f);
        else if (i < 2 * HD + FIN) v = g_z.att[0][g * FIN + (i - 2 * HD)];
        else                   v = g_z.att[1][g * FIN + (i - 2 * HD - FIN)];
        cat[i] = v;
    }
    __syncthreads();
    float acc = lb0[j];
#pragma unroll 8
    for (int i = 0; i < 2 * HD + 2 * FIN; i++)
        acc += cat[i] * lW0[i * HD + j];
    red[j] = fmaxf(acc, 0.f) * lW1[j];
    __syncthreads();
    if (j == 0) {
        float s = lb1[0];
        for (int t = 0; t < HD; t++) s += red[t];
        out[g] = s;
    }
}

// ---------------- host launcher ----------------------------------------------
extern "C" void kernel_launch(void* const* d_in, const int* in_sizes, int n_in,
                              void* d_out, int out_size) {
    const float* xp  = (const float*)d_in[0];
    const float* xd  = (const float*)d_in[1];
    const int*   eip = (const int*)d_in[4];
    const int*   eid = (const int*)d_in[5];
    const int*   bp  = (const int*)d_in[6];
    const int*   bd  = (const int*)d_in[7];
    const float* Wp0 = (const float*)d_in[8],  *bp0 = (const float*)d_in[9];
    const float* Wp1 = (const float*)d_in[10], *bp1 = (const float*)d_in[11];
    const float* Wp2 = (const float*)d_in[12], *bp2 = (const float*)d_in[13];
    const float* Wd0 = (const float*)d_in[14], *bd0 = (const float*)d_in[15];
    const float* Wd1 = (const float*)d_in[16], *bd1 = (const float*)d_in[17];
    const float* Wd2 = (const float*)d_in[18], *bd2 = (const float*)d_in[19];
    const float* gW1 = (const float*)d_in[20], *gb1 = (const float*)d_in[21];
    const float* gW2 = (const float*)d_in[22], *gb2 = (const float*)d_in[23];
    const float* lW0 = (const float*)d_in[24], *lb0 = (const float*)d_in[25];
    const float* lW1 = (const float*)d_in[26], *lb1 = (const float*)d_in[27];

    const int TB = 256;
    const int GB_E2 = (NE2 + TB - 1) / TB;
    const int GB_C16 = (NN2 * 16 + TB - 1) / TB;
    const int GB_H8  = (NN2 * 8 + TB - 1) / TB;
    const int GB_H12 = (NN2 * 12 + TB - 1) / TB;
    const int GEMM_GRID = 782;                       // 391 tiles x 2 sides
    const int SMEM96 = (128 + 96 + 96) * (96 + 8) * 2;   // 66560 B
    const int SMEM64 = (128 + 96 + 96) * (64 + 8) * 2;   // 46080 B

    static cudaStream_t s2 = nullptr;
    static cudaEvent_t ev1 = nullptr, evT = nullptr, ev2 = nullptr;
    static int inited = 0;
    if (!inited) {
        cudaFuncSetAttribute(k_gemm_mma, cudaFuncAttributeMaxDynamicSharedMemorySize, SMEM96);
        cudaStreamCreateWithFlags(&s2, cudaStreamNonBlocking);
        cudaEventCreateWithFlags(&ev1, cudaEventDisableTiming);
        cudaEventCreateWithFlags(&evT, cudaEventDisableTiming);
        cudaEventCreateWithFlags(&ev2, cudaEventDisableTiming);
        inited = 1;
    }

    void* xh_dev = nullptr;  cudaGetSymbolAddress(&xh_dev, g_xh);
    void* hh_dev = nullptr;  cudaGetSymbolAddress(&hh_dev, g_hh);
    void* deg_dev = nullptr; cudaGetSymbolAddress(&deg_dev, g_deg);
    void* z_dev = nullptr;   cudaGetSymbolAddress(&z_dev, g_z);

    // ---- fork ----
    cudaEventRecord(ev1, 0);
    cudaStreamWaitEvent(s2, ev1, 0);

    // stream B: zero-init, tohalf (needed by gathers), then gate+attpool
    cudaMemsetAsync(z_dev, 0, sizeof(ZeroBlk), s2);
    k_tohalf<<<GB_C16, TB, 0, s2>>>((const float4*)xp, (const float4*)xd);
    cudaEventRecord(evT, s2);                 // gathers need only this from B
    k_gate<<<(NN2 + 7) / 8, 256, 0, s2>>>(xp, xd, bp, bd, gW1, gb1, gW2, gb2);
    k_attpool<<<GB_C16, TB, 0, s2>>>(xp, xd, bp, bd);
    cudaEventRecord(ev2, s2);                 // k_final needs this

    // stream A (default): CSR build
    cudaMemsetAsync(deg_dev, 0, NN2 * sizeof(int), 0);
    k_deg<<<GB_E2, TB>>>(eip, eid);
    k_scan1<<<NSCB2, SCB>>>();
    k_scan3<<<NSCB2, SCB>>>();
    k_csrfill<<<GB_E2, TB>>>(eip, eid);

    // join #1: gathers need tohalf; attpool continues concurrently on B
    cudaStreamWaitEvent(0, evT, 0);

    // layer 0: gather x (K=64) -> aggh; HMMA GEMM 64->96 (+relu) -> g_hh
    k_gatherh<<<GB_H8, TB>>>((const int4*)xh_dev, 8);
    k_gemm_mma<<<GEMM_GRID, 256, SMEM64>>>(Wp0, Wd0, bp0, bd0, 64, 1, 0, bp, bd);
    // layer 1
    k_gatherh<<<GB_H12, TB>>>((const int4*)hh_dev, 12);
    k_gemm_mma<<<GEMM_GRID, 256, SMEM96>>>(Wp1, Wd1, bp1, bd1, 96, 1, 0, bp, bd);
    // layer 2 (+ fused mean-pool sums)
    k_gatherh<<<GB_H12, TB>>>((const int4*)hh_dev, 12);
    k_gemm_mma<<<GEMM_GRID, 256, SMEM96>>>(Wp2, Wd2, bp2, bd2, 96, 0, 1, bp, bd);

    // join #2: k_final reads g_z.att / g_z.gden written on stream B
    cudaStreamWaitEvent(0, ev2, 0);
    k_final<<<NG, HD>>>(lW0, lb0, lW1, lb1, (float*)d_out);
}

// round 13
// speedup vs baseline: 1.6883x; 1.0866x over previous
#include <cuda_runtime.h>
#include <cuda_fp16.h>
#include <math.h>

#define NN 50000
#define NN2 100000
#define NE 800000
#define NE2 1600000
#define FIN 64
#define HD 96
#define NG 256
#define SCB 512
#define NSCB2 ((NN2 + SCB - 1) / SCB)   // 196

// weight pack offsets (halves): [L0s0,L0s1, L1s0,L1s1, L2s0,L2s1], transposed [n][k]
#define WOFF_L0 0
#define WOFF_L1 12288            // 2*64*96
#define WOFF_L2 30720            // + 2*96*96
#define WTOT    49152            // + 2*96*96

// ---------------- scratch (device globals; no runtime allocation) -----------
__device__ __align__(16) __half g_hh[NN2 * HD];   // layer outputs, fp16
__device__ __align__(16) __half g_xh[NN2 * FIN];  // input features, fp16
__device__ __align__(16) __half g_aggh[NN2 * HD]; // gather outputs, fp16
__device__ __align__(16) __half g_whi[WTOT];      // weights hi, fp16, [n][k]
__device__ __align__(16) __half g_wlo[WTOT];      // weights lo (residual)
__device__ float g_dinv[NN2];
__device__ int   g_deg[NN2];
__device__ int   g_coff[NN2 + 1];
__device__ int   g_cur[NN2];
__device__ __align__(8) int2 g_edge[NE2];         // (local src, norm-bits)
__device__ int   g_bsum[256];
__device__ float g_gate[NN2];

// zero-initialized-per-iteration block (single memset)
struct __align__(16) ZeroBlk {
    float gden[2][NG];
    int   cnt[2][NG];
    float att[2][NG * FIN];
    float pool[2][NG * HD];
};
__device__ ZeroBlk g_z;

// ---------------- helpers ----------------------------------------------------
__device__ __forceinline__ void red4(float* p, float4 v) {
    asm volatile("red.global.add.v4.f32 [%0], {%1,%2,%3,%4};"
                 :: "l"(p), "f"(v.x), "f"(v.y), "f"(v.z), "f"(v.w) : "memory");
}
__device__ __forceinline__ void red2(float* p, float a, float b) {
    asm volatile("red.global.add.v2.f32 [%0], {%1,%2};"
                 :: "l"(p), "f"(a), "f"(b) : "memory");
}

__device__ __forceinline__ void mma16816(float* c, const unsigned* a, unsigned b0, unsigned b1) {
    asm volatile(
        "mma.sync.aligned.m16n8k16.row.col.f32.f16.f16.f32 "
        "{%0,%1,%2,%3}, {%4,%5,%6,%7}, {%8,%9}, {%0,%1,%2,%3};"
        : "+f"(c[0]), "+f"(c[1]), "+f"(c[2]), "+f"(c[3])
        : "r"(a[0]), "r"(a[1]), "r"(a[2]), "r"(a[3]), "r"(b0), "r"(b1));
}

// acc[0..7] += w * (8 halves in raw)
__device__ __forceinline__ void fma8(int4 raw, float w, float* acc) {
    __half2* h = reinterpret_cast<__half2*>(&raw);
#pragma unroll
    for (int i = 0; i < 4; i++) {
        float2 f = __half22float2(h[i]);
        acc[2 * i]     += w * f.x;
        acc[2 * i + 1] += w * f.y;
    }
}

// ---------------- weight preconversion: fp32 [k][n] -> hi/lo fp16 [n][k] -------
__global__ void k_prepw(const float* __restrict__ Wp0, const float* __restrict__ Wd0,
                        const float* __restrict__ Wp1, const float* __restrict__ Wd1,
                        const float* __restrict__ Wp2, const float* __restrict__ Wd2) {
    int idx = blockIdx.x * blockDim.x + threadIdx.x;
    if (idx >= WTOT) return;
    const float* W;
    int K, base, e;
    if (idx < WOFF_L1) {
        int t = idx - WOFF_L0;  K = 64;
        int side = t / 6144;    e = t - side * 6144;
        W = side ? Wd0 : Wp0;   base = WOFF_L0 + side * 6144;
    } else if (idx < WOFF_L2) {
        int t = idx - WOFF_L1;  K = 96;
        int side = t / 9216;    e = t - side * 9216;
        W = side ? Wd1 : Wp1;   base = WOFF_L1 + side * 9216;
    } else {
        int t = idx - WOFF_L2;  K = 96;
        int side = t / 9216;    e = t - side * 9216;
        W = side ? Wd2 : Wp2;   base = WOFF_L2 + side * 9216;
    }
    int k = e / HD, n = e - k * HD;
    float w = __ldg(&W[k * HD + n]);
    __half hi = __float2half_rn(w);
    __half lo = __float2half_rn(w - __half2float(hi));
    g_whi[base + n * K + k] = hi;
    g_wlo[base + n * K + k] = lo;
}

// ---------------- input conversion ---------------------------------------------
__global__ void k_tohalf(const float4* __restrict__ xp, const float4* __restrict__ xd) {
    int idx = blockIdx.x * blockDim.x + threadIdx.x;      // NN2 * 16
    if (idx >= NN2 * 16) return;
    int n = idx >> 4;
    int side = (n >= NN);
    int nl = n - side * NN;
    float4 v = __ldg(&(side ? xd : xp)[nl * 16 + (idx & 15)]);
    __half2 h0 = __floats2half2_rn(v.x, v.y);
    __half2 h1 = __floats2half2_rn(v.z, v.w);
    uint2 u;
    u.x = *(unsigned*)&h0; u.y = *(unsigned*)&h1;
    ((uint2*)g_xh)[idx] = u;
}

__global__ void k_deg(const int* __restrict__ eip, const int* __restrict__ eid) {
    int e = blockIdx.x * blockDim.x + threadIdx.x;
    if (e >= NE2) return;
    int side = (e >= NE);
    int el = e - side * NE;
    const int* ei = side ? eid : eip;
    atomicAdd(&g_deg[side * NN + ei[NE + el]], 1);
}

// ---------------- CSR build ----------------------------------------------------
__global__ void k_scan1() {
    __shared__ int s[SCB];
    int i = blockIdx.x * SCB + threadIdx.x;
    s[threadIdx.x] = (i < NN2) ? g_deg[i] : 0;
    __syncthreads();
    for (int o = SCB / 2; o > 0; o >>= 1) {
        if (threadIdx.x < o) s[threadIdx.x] += s[threadIdx.x + o];
        __syncthreads();
    }
    if (threadIdx.x == 0) g_bsum[blockIdx.x] = s[0];
}

__global__ void k_scan3() {
    __shared__ int sb[SCB];
    int t = threadIdx.x;
    sb[t] = (t < blockIdx.x) ? g_bsum[t] : 0;
    __syncthreads();
    for (int o = SCB / 2; o > 0; o >>= 1) {
        if (t < o) sb[t] += sb[t + o];
        __syncthreads();
    }
    int boff = sb[0];
    __syncthreads();
    int i = blockIdx.x * SCB + t;
    int v = (i < NN2) ? g_deg[i] : 0;
    sb[t] = v;
    __syncthreads();
    for (int o = 1; o < SCB; o <<= 1) {
        int a = (t >= o) ? sb[t - o] : 0;
        __syncthreads();
        sb[t] += a;
        __syncthreads();
    }
    if (i < NN2) {
        int off = boff + sb[t] - v;                 // exclusive
        g_coff[i] = off;
        g_cur[i] = off;
        g_dinv[i] = rsqrtf((float)v + 1.0f);
    }
    if (blockIdx.x == NSCB2 - 1 && t == SCB - 1) g_coff[NN2] = boff + sb[t];
}

__global__ void k_csrfill(const int* __restrict__ eip, const int* __restrict__ eid) {
    int e = blockIdx.x * blockDim.x + threadIdx.x;
    if (e >= NE2) return;
    int side = (e >= NE);
    int el = e - side * NE;
    const int* ei = side ? eid : eip;
    int s = ei[el], d = ei[NE + el];
    int base = side * NN;
    float norm = g_dinv[base + s] * g_dinv[base + d];
    int slot = atomicAdd(&g_cur[base + d], 1);
    g_edge[slot] = make_int2(s, __float_as_int(norm));
}

// ---------------- attention gate (both sides) ----------------------------------
__global__ void k_gate(const float* __restrict__ xp, const float* __restrict__ xd,
                       const int* __restrict__ bp, const int* __restrict__ bd,
                       const float* __restrict__ gW1, const float* __restrict__ gb1,
                       const float* __restrict__ gW2, const float* __restrict__ gb2) {
    int lane = threadIdx.x & 31;
    int n = blockIdx.x * (blockDim.x >> 5) + (threadIdx.x >> 5);
    if (n >= NN2) return;
    int side = (n >= NN);
    int nl = n - side * NN;
    const float* x = side ? xd : xp;
    const int* batch = side ? bd : bp;
    float xa = x[nl * FIN + lane];
    float xb = x[nl * FIN + 32 + lane];
    float acc0 = gb1[lane];
    float acc1 = gb1[lane + 32];
#pragma unroll
    for (int k = 0; k < FIN; k++) {
        float xk = __shfl_sync(0xffffffffu, (k < 32) ? xa : xb, k & 31);
        acc0 += xk * gW1[k * FIN + lane];
        acc1 += xk * gW1[k * FIN + lane + 32];
    }
    float h = fmaxf(acc0, 0.f) * gW2[lane] + fmaxf(acc1, 0.f) * gW2[lane + 32];
#pragma unroll
    for (int o = 16; o > 0; o >>= 1) h += __shfl_down_sync(0xffffffffu, h, o);
    if (lane == 0) {
        float e = expf(h + gb2[0]);        // gates tiny: no max-shift needed
        g_gate[n] = e;
        int b = batch[nl];
        atomicAdd(&g_z.gden[side][b], e);
        atomicAdd(&g_z.cnt[side][b], 1);
    }
}

__global__ void k_attpool(const float* __restrict__ xp, const float* __restrict__ xd,
                          const int* __restrict__ bp, const int* __restrict__ bd) {
    int idx = blockIdx.x * blockDim.x + threadIdx.x;     // NN2 * 16
    if (idx >= NN2 * (FIN / 4)) return;
    int n = idx >> 4, j = idx & 15;
    int side = (n >= NN);
    int nl = n - side * NN;
    int b = side ? bd[nl] : bp[nl];
    float alpha = g_gate[n] / g_z.gden[side][b];
    const float4* x4 = side ? (const float4*)xd : (const float4*)xp;
    float4 v = __ldg(&x4[nl * (FIN / 4) + j]);
    v.x *= alpha; v.y *= alpha; v.z *= alpha; v.w *= alpha;
    red4(&g_z.att[side][b * FIN + j * 4], v);
}

// ---------------- fp16 CSR gather -> fp16 agg (4-wide edge unroll, R10) --------
__global__ void k_gatherh(const int4* __restrict__ f16, int K8) {
    int idx = blockIdx.x * blockDim.x + threadIdx.x;
    if (idx >= NN2 * K8) return;
    int n = idx / K8, j = idx - n * K8;
    int base = (n >= NN) ? NN : 0;
    float dv = g_dinv[n];
    float acc[8] = {0.f, 0.f, 0.f, 0.f, 0.f, 0.f, 0.f, 0.f};
    fma8(__ldg(&f16[(size_t)n * K8 + j]), dv * dv, acc);
    int p = __ldg(&g_coff[n]);
    int end = __ldg(&g_coff[n + 1]);
    for (; p + 3 < end; p += 4) {
        int2 e0 = __ldg(&g_edge[p]);
        int2 e1 = __ldg(&g_edge[p + 1]);
        int2 e2 = __ldg(&g_edge[p + 2]);
        int2 e3 = __ldg(&g_edge[p + 3]);
        int4 a0 = __ldg(&f16[(size_t)(base + e0.x) * K8 + j]);
        int4 a1 = __ldg(&f16[(size_t)(base + e1.x) * K8 + j]);
        int4 a2 = __ldg(&f16[(size_t)(base + e2.x) * K8 + j]);
        int4 a3 = __ldg(&f16[(size_t)(base + e3.x) * K8 + j]);
        fma8(a0, __int_as_float(e0.y), acc);
        fma8(a1, __int_as_float(e1.y), acc);
        fma8(a2, __int_as_float(e2.y), acc);
        fma8(a3, __int_as_float(e3.y), acc);
    }
    for (; p < end; p++) {
        int2 e0 = __ldg(&g_edge[p]);
        fma8(__ldg(&f16[(size_t)(base + e0.x) * K8 + j]), __int_as_float(e0.y), acc);
    }
    __half2 h0 = __floats2half2_rn(acc[0], acc[1]);
    __half2 h1 = __floats2half2_rn(acc[2], acc[3]);
    __half2 h2 = __floats2half2_rn(acc[4], acc[5]);
    __half2 h3 = __floats2half2_rn(acc[6], acc[7]);
    int4 o;
    o.x = *(int*)&h0; o.y = *(int*)&h1; o.z = *(int*)&h2; o.w = *(int*)&h3;
    ((int4*)g_aggh)[idx] = o;
}

// ---------------- HMMA GEMM: out[rows,96] = aggh[rows,K] @ W[K,96] + b ----------
// Weights pre-split hi/lo fp16 transposed [n][k]; pure int4 copies into smem.
__global__ void __launch_bounds__(256) k_gemm_mma(
        int woff,
        const float* __restrict__ bp, const float* __restrict__ bd,
        int K, int reluOut, int fusePool,
        const int* __restrict__ batch_p, const int* __restrict__ batch_d) {
    extern __shared__ __half sm[];
    const int KS = K + 8;
    __half* As  = sm;                     // 128 x KS
    __half* Bhi = As + 128 * KS;          // 96 x KS  ([n][k])
    __half* Blo = Bhi + 96 * KS;
    const int side = blockIdx.x & 1;
    const int tile = blockIdx.x >> 1;
    const int rowBase = tile * 128;
    const float* bias = side ? bd : bp;
    const int* batch = side ? batch_d : batch_p;
    const int tid = threadIdx.x;
    const int K8 = K >> 3;

    // copy preconverted weights (int4 = 8 halves)
    const int4* Wh4 = (const int4*)(g_whi + woff + side * (HD * K));
    const int4* Wl4 = (const int4*)(g_wlo + woff + side * (HD * K));
    for (int i = tid; i < HD * K8; i += 256) {
        int r = i / K8, j = i - r * K8;
        *(int4*)&Bhi[r * KS + j * 8] = __ldg(&Wh4[i]);
        *(int4*)&Blo[r * KS + j * 8] = __ldg(&Wl4[i]);
    }
    const int4* Ah = (const int4*)g_aggh;
    for (int i = tid; i < 128 * K8; i += 256) {
        int r = i / K8, j = i - r * K8;
        int row = rowBase + r;
        int4 v = make_int4(0, 0, 0, 0);
        if (row < NN) v = __ldg(&Ah[(size_t)(side * NN + row) * K8 + j]);
        *(int4*)&As[r * KS + j * 8] = v;
    }
    __syncthreads();

    const int warp = tid >> 5;
    const int lane = tid & 31;
    const int g = lane >> 2;
    const int tg = lane & 3;
    const int warpRow = warp * 16;

    float c[12][4];
#pragma unroll
    for (int nt = 0; nt < 12; nt++)
#pragma unroll
        for (int q = 0; q < 4; q++) c[nt][q] = 0.f;

    const int nk = K >> 4;
    for (int ks = 0; ks < nk; ks++) {
        unsigned a[4];
        const __half* arow0 = &As[(warpRow + g) * KS + ks * 16 + tg * 2];
        const __half* arow1 = arow0 + 8 * KS;
        a[0] = *(const unsigned*)arow0;
        a[1] = *(const unsigned*)arow1;
        a[2] = *(const unsigned*)(arow0 + 8);
        a[3] = *(const unsigned*)(arow1 + 8);
#pragma unroll
        for (int nt = 0; nt < 12; nt++) {
            const __half* brow = &Bhi[(nt * 8 + g) * KS + ks * 16 + tg * 2];
            unsigned b0 = *(const unsigned*)brow;
            unsigned b1 = *(const unsigned*)(brow + 8);
            mma16816(c[nt], a, b0, b1);
            const __half* brl = &Blo[(nt * 8 + g) * KS + ks * 16 + tg * 2];
            unsigned l0 = *(const unsigned*)brl;
            unsigned l1 = *(const unsigned*)(brl + 8);
            mma16816(c[nt], a, l0, l1);
        }
    }

    int row0 = rowBase + warpRow + g;
    int row1 = row0 + 8;
#pragma unroll
    for (int nt = 0; nt < 12; nt++) {
        int col = nt * 8 + tg * 2;
        float bx = __ldg(&bias[col]);
        float by = __ldg(&bias[col + 1]);
        float v00 = c[nt][0] + bx, v01 = c[nt][1] + by;
        float v10 = c[nt][2] + bx, v11 = c[nt][3] + by;
        if (!fusePool) {
            if (reluOut) {
                v00 = fmaxf(v00, 0.f); v01 = fmaxf(v01, 0.f);
                v10 = fmaxf(v10, 0.f); v11 = fmaxf(v11, 0.f);
            }
            if (row0 < NN) {
                __half2 h = __floats2half2_rn(v00, v01);
                *(unsigned*)&g_hh[(size_t)(side * NN + row0) * HD + col] = *(unsigned*)&h;
            }
            if (row1 < NN) {
                __half2 h = __floats2half2_rn(v10, v11);
                *(unsigned*)&g_hh[(size_t)(side * NN + row1) * HD + col] = *(unsigned*)&h;
            }
        } else {
            if (row0 < NN) red2(&g_z.pool[side][batch[row0] * HD + col], v00, v01);
            if (row1 < NN) red2(&g_z.pool[side][batch[row1] * HD + col], v10, v11);
        }
    }
}

// ---------------- final MLP ---------------------------------------------------
__global__ void k_final(const float* __restrict__ lW0, const float* __restrict__ lb0,
                        const float* __restrict__ lW1, const float* __restrict__ lb1,
                        float* __restrict__ out) {
    int g = blockIdx.x;
    int j = threadIdx.x;                                 // 96 threads
    __shared__ float cat[2 * HD + 2 * FIN];              // 320
    __shared__ float red[HD];
    for (int i = j; i < 2 * HD + 2 * FIN; i += HD) {
        float v;
        if (i < HD)            v = g_z.pool[0][g * HD + i] / fmaxf((float)g_z.cnt[0][g], 1.f);
        else if (i < 2 * HD)   v = g_z.pool[1][g * HD + (i - HD)] / fmaxf((float)g_z.cnt[1][g], 1.f);
        else if (i < 2 * HD + FIN) v = g_z.att[0][g * FIN + (i - 2 * HD)];
        else                   v = g_z.att[1][g * FIN + (i - 2 * HD - FIN)];
        cat[i] = v;
    }
    __syncthreads();
    float acc = lb0[j];
#pragma unroll 8
    for (int i = 0; i < 2 * HD + 2 * FIN; i++)
        acc += cat[i] * lW0[i * HD + j];
    red[j] = fmaxf(acc, 0.f) * lW1[j];
    __syncthreads();
    if (j == 0) {
        float s = lb1[0];
        for (int t = 0; t < HD; t++) s += red[t];
        out[g] = s;
    }
}

// ---------------- host launcher ----------------------------------------------
extern "C" void kernel_launch(void* const* d_in, const int* in_sizes, int n_in,
                              void* d_out, int out_size) {
    const float* xp  = (const float*)d_in[0];
    const float* xd  = (const float*)d_in[1];
    const int*   eip = (const int*)d_in[4];
    const int*   eid = (const int*)d_in[5];
    const int*   bp  = (const int*)d_in[6];
    const int*   bd  = (const int*)d_in[7];
    const float* Wp0 = (const float*)d_in[8],  *bp0 = (const float*)d_in[9];
    const float* Wp1 = (const float*)d_in[10], *bp1 = (const float*)d_in[11];
    const float* Wp2 = (const float*)d_in[12], *bp2 = (const float*)d_in[13];
    const float* Wd0 = (const float*)d_in[14], *bd0 = (const float*)d_in[15];
    const float* Wd1 = (const float*)d_in[16], *bd1 = (const float*)d_in[17];
    const float* Wd2 = (const float*)d_in[18], *bd2 = (const float*)d_in[19];
    const float* gW1 = (const float*)d_in[20], *gb1 = (const float*)d_in[21];
    const float* gW2 = (const float*)d_in[22], *gb2 = (const float*)d_in[23];
    const float* lW0 = (const float*)d_in[24], *lb0 = (const float*)d_in[25];
    const float* lW1 = (const float*)d_in[26], *lb1 = (const float*)d_in[27];

    const int TB = 256;
    const int GB_E2 = (NE2 + TB - 1) / TB;
    const int GB_C16 = (NN2 * 16 + TB - 1) / TB;
    const int GB_H8  = (NN2 * 8 + TB - 1) / TB;
    const int GB_H12 = (NN2 * 12 + TB - 1) / TB;
    const int GEMM_GRID = 782;                       // 391 tiles x 2 sides
    const int SMEM96 = (128 + 96 + 96) * (96 + 8) * 2;   // 66560 B
    const int SMEM64 = (128 + 96 + 96) * (64 + 8) * 2;   // 46080 B

    static cudaStream_t s2 = nullptr;
    static cudaEvent_t ev1 = nullptr, evT = nullptr, ev2 = nullptr;
    static int inited = 0;
    if (!inited) {
        cudaFuncSetAttribute(k_gemm_mma, cudaFuncAttributeMaxDynamicSharedMemorySize, SMEM96);
        cudaStreamCreateWithFlags(&s2, cudaStreamNonBlocking);
        cudaEventCreateWithFlags(&ev1, cudaEventDisableTiming);
        cudaEventCreateWithFlags(&evT, cudaEventDisableTiming);
        cudaEventCreateWithFlags(&ev2, cudaEventDisableTiming);
        inited = 1;
    }

    void* xh_dev = nullptr;  cudaGetSymbolAddress(&xh_dev, g_xh);
    void* hh_dev = nullptr;  cudaGetSymbolAddress(&hh_dev, g_hh);
    void* deg_dev = nullptr; cudaGetSymbolAddress(&deg_dev, g_deg);
    void* z_dev = nullptr;   cudaGetSymbolAddress(&z_dev, g_z);

    // ---- fork ----
    cudaEventRecord(ev1, 0);
    cudaStreamWaitEvent(s2, ev1, 0);

    // stream B: zero-init, weight prep + tohalf (needed by GEMM/gather), gate+attpool
    cudaMemsetAsync(z_dev, 0, sizeof(ZeroBlk), s2);
    k_prepw<<<(WTOT + TB - 1) / TB, TB, 0, s2>>>(Wp0, Wd0, Wp1, Wd1, Wp2, Wd2);
    k_tohalf<<<GB_C16, TB, 0, s2>>>((const float4*)xp, (const float4*)xd);
    cudaEventRecord(evT, s2);                 // layer-0 work needs prepw+tohalf from B
    k_gate<<<(NN2 + 7) / 8, 256, 0, s2>>>(xp, xd, bp, bd, gW1, gb1, gW2, gb2);
    k_attpool<<<GB_C16, TB, 0, s2>>>(xp, xd, bp, bd);
    cudaEventRecord(ev2, s2);                 // k_final needs this

    // stream A (default): CSR build
    cudaMemsetAsync(deg_dev, 0, NN2 * sizeof(int), 0);
    k_deg<<<GB_E2, TB>>>(eip, eid);
    k_scan1<<<NSCB2, SCB>>>();
    k_scan3<<<NSCB2, SCB>>>();
    k_csrfill<<<GB_E2, TB>>>(eip, eid);

    // join #1: gathers/GEMMs need tohalf + prepw; attpool continues on B
    cudaStreamWaitEvent(0, evT, 0);

    // layer 0: gather x (K=64) -> aggh; HMMA GEMM 64->96 (+relu) -> g_hh
    k_gatherh<<<GB_H8, TB>>>((const int4*)xh_dev, 8);
    k_gemm_mma<<<GEMM_GRID, 256, SMEM64>>>(WOFF_L0, bp0, bd0, 64, 1, 0, bp, bd);
    // layer 1
    k_gatherh<<<GB_H12, TB>>>((const int4*)hh_dev, 12);
    k_gemm_mma<<<GEMM_GRID, 256, SMEM96>>>(WOFF_L1, bp1, bd1, 96, 1, 0, bp, bd);
    // layer 2 (+ fused mean-pool sums)
    k_gatherh<<<GB_H12, TB>>>((const int4*)hh_dev, 12);
    k_gemm_mma<<<GEMM_GRID, 256, SMEM96>>>(WOFF_L2, bp2, bd2, 96, 0, 1, bp, bd);

    // join #2: k_final reads g_z.att / g_z.gden written on stream B
    cudaStreamWaitEvent(0, ev2, 0);
    k_final<<<NG, HD>>>(lW0, lb0, lW1, lb1, (float*)d_out);
}

// round 14
// speedup vs baseline: 1.7437x; 1.0328x over previous
#include <cuda_runtime.h>
#include <cuda_fp16.h>
#include <math.h>

#define NN 50000
#define NN2 100000
#define NE 800000
#define NE2 1600000
#define FIN 64
#define HD 96
#define NG 256
#define SCB 512
#define NSCB2 ((NN2 + SCB - 1) / SCB)   // 196

// weight pack offsets (halves): [L0s0,L0s1, L1s0,L1s1, L2s0,L2s1], transposed [n][k]
#define WOFF_L0 0
#define WOFF_L1 12288            // 2*64*96
#define WOFF_L2 30720            // + 2*96*96
#define WTOT    49152            // + 2*96*96

// ---------------- scratch (device globals; no runtime allocation) -----------
__device__ __align__(16) __half g_hh[NN2 * HD];   // layer outputs, fp16
__device__ __align__(16) __half g_xh[NN2 * FIN];  // input features, fp16
__device__ __align__(16) __half g_aggh[NN2 * HD]; // gather outputs, fp16
__device__ __align__(16) __half g_whi[WTOT];      // weights hi, fp16, [n][k]
__device__ __align__(16) __half g_wlo[WTOT];      // weights lo (residual)
__device__ float g_dinv[NN2];
__device__ int   g_deg[NN2];
__device__ int   g_coff[NN2 + 1];
__device__ int   g_cur[NN2];
__device__ __align__(8) int2 g_edge[NE2];         // (local src, norm-bits)
__device__ int   g_bsum[256];
__device__ float g_gate[NN2];

// zero-initialized-per-iteration block (single memset)
struct __align__(16) ZeroBlk {
    float gden[2][NG];
    int   cnt[2][NG];
    float att[2][NG * FIN];
    float pool[2][NG * HD];
};
__device__ ZeroBlk g_z;

// ---------------- helpers ----------------------------------------------------
__device__ __forceinline__ void red4(float* p, float4 v) {
    asm volatile("red.global.add.v4.f32 [%0], {%1,%2,%3,%4};"
                 :: "l"(p), "f"(v.x), "f"(v.y), "f"(v.z), "f"(v.w) : "memory");
}
__device__ __forceinline__ void red2(float* p, float a, float b) {
    asm volatile("red.global.add.v2.f32 [%0], {%1,%2};"
                 :: "l"(p), "f"(a), "f"(b) : "memory");
}

__device__ __forceinline__ void mma16816(float* c, const unsigned* a, unsigned b0, unsigned b1) {
    asm volatile(
        "mma.sync.aligned.m16n8k16.row.col.f32.f16.f16.f32 "
        "{%0,%1,%2,%3}, {%4,%5,%6,%7}, {%8,%9}, {%0,%1,%2,%3};"
        : "+f"(c[0]), "+f"(c[1]), "+f"(c[2]), "+f"(c[3])
        : "r"(a[0]), "r"(a[1]), "r"(a[2]), "r"(a[3]), "r"(b0), "r"(b1));
}

// acc[0..7] += w * (8 halves in raw)
__device__ __forceinline__ void fma8(int4 raw, float w, float* acc) {
    __half2* h = reinterpret_cast<__half2*>(&raw);
#pragma unroll
    for (int i = 0; i < 4; i++) {
        float2 f = __half22float2(h[i]);
        acc[2 * i]     += w * f.x;
        acc[2 * i + 1] += w * f.y;
    }
}

// ---------------- weight preconversion: fp32 [k][n] -> hi/lo fp16 [n][k] -------
__global__ void k_prepw(const float* __restrict__ Wp0, const float* __restrict__ Wd0,
                        const float* __restrict__ Wp1, const float* __restrict__ Wd1,
                        const float* __restrict__ Wp2, const float* __restrict__ Wd2) {
    int idx = blockIdx.x * blockDim.x + threadIdx.x;
    if (idx >= WTOT) return;
    const float* W;
    int K, base, e;
    if (idx < WOFF_L1) {
        int t = idx - WOFF_L0;  K = 64;
        int side = t / 6144;    e = t - side * 6144;
        W = side ? Wd0 : Wp0;   base = WOFF_L0 + side * 6144;
    } else if (idx < WOFF_L2) {
        int t = idx - WOFF_L1;  K = 96;
        int side = t / 9216;    e = t - side * 9216;
        W = side ? Wd1 : Wp1;   base = WOFF_L1 + side * 9216;
    } else {
        int t = idx - WOFF_L2;  K = 96;
        int side = t / 9216;    e = t - side * 9216;
        W = side ? Wd2 : Wp2;   base = WOFF_L2 + side * 9216;
    }
    int k = e / HD, n = e - k * HD;
    float w = __ldg(&W[k * HD + n]);
    __half hi = __float2half_rn(w);
    __half lo = __float2half_rn(w - __half2float(hi));
    g_whi[base + n * K + k] = hi;
    g_wlo[base + n * K + k] = lo;
}

// ---------------- input conversion ---------------------------------------------
__global__ void k_tohalf(const float4* __restrict__ xp, const float4* __restrict__ xd) {
    int idx = blockIdx.x * blockDim.x + threadIdx.x;      // NN2 * 16
    if (idx >= NN2 * 16) return;
    int n = idx >> 4;
    int side = (n >= NN);
    int nl = n - side * NN;
    float4 v = __ldg(&(side ? xd : xp)[nl * 16 + (idx & 15)]);
    __half2 h0 = __floats2half2_rn(v.x, v.y);
    __half2 h1 = __floats2half2_rn(v.z, v.w);
    uint2 u;
    u.x = *(unsigned*)&h0; u.y = *(unsigned*)&h1;
    ((uint2*)g_xh)[idx] = u;
}

__global__ void k_deg(const int* __restrict__ eip, const int* __restrict__ eid) {
    int e = blockIdx.x * blockDim.x + threadIdx.x;
    if (e >= NE2) return;
    int side = (e >= NE);
    int el = e - side * NE;
    const int* ei = side ? eid : eip;
    atomicAdd(&g_deg[side * NN + ei[NE + el]], 1);
}

// ---------------- CSR build ----------------------------------------------------
__global__ void k_scan1() {
    __shared__ int s[SCB];
    int i = blockIdx.x * SCB + threadIdx.x;
    s[threadIdx.x] = (i < NN2) ? g_deg[i] : 0;
    __syncthreads();
    for (int o = SCB / 2; o > 0; o >>= 1) {
        if (threadIdx.x < o) s[threadIdx.x] += s[threadIdx.x + o];
        __syncthreads();
    }
    if (threadIdx.x == 0) g_bsum[blockIdx.x] = s[0];
}

__global__ void k_scan3() {
    __shared__ int sb[SCB];
    int t = threadIdx.x;
    sb[t] = (t < blockIdx.x) ? g_bsum[t] : 0;
    __syncthreads();
    for (int o = SCB / 2; o > 0; o >>= 1) {
        if (t < o) sb[t] += sb[t + o];
        __syncthreads();
    }
    int boff = sb[0];
    __syncthreads();
    int i = blockIdx.x * SCB + t;
    int v = (i < NN2) ? g_deg[i] : 0;
    sb[t] = v;
    __syncthreads();
    for (int o = 1; o < SCB; o <<= 1) {
        int a = (t >= o) ? sb[t - o] : 0;
        __syncthreads();
        sb[t] += a;
        __syncthreads();
    }
    if (i < NN2) {
        int off = boff + sb[t] - v;                 // exclusive
        g_coff[i] = off;
        g_cur[i] = off;
        g_dinv[i] = rsqrtf((float)v + 1.0f);
    }
    if (blockIdx.x == NSCB2 - 1 && t == SCB - 1) g_coff[NN2] = boff + sb[t];
}

__global__ void k_csrfill(const int* __restrict__ eip, const int* __restrict__ eid) {
    int e = blockIdx.x * blockDim.x + threadIdx.x;
    if (e >= NE2) return;
    int side = (e >= NE);
    int el = e - side * NE;
    const int* ei = side ? eid : eip;
    int s = ei[el], d = ei[NE + el];
    int base = side * NN;
    float norm = g_dinv[base + s] * g_dinv[base + d];
    int slot = atomicAdd(&g_cur[base + d], 1);
    g_edge[slot] = make_int2(s, __float_as_int(norm));
}

// ---------------- attention gate (both sides) ----------------------------------
__global__ void k_gate(const float* __restrict__ xp, const float* __restrict__ xd,
                       const int* __restrict__ bp, const int* __restrict__ bd,
                       const float* __restrict__ gW1, const float* __restrict__ gb1,
                       const float* __restrict__ gW2, const float* __restrict__ gb2) {
    int lane = threadIdx.x & 31;
    int n = blockIdx.x * (blockDim.x >> 5) + (threadIdx.x >> 5);
    if (n >= NN2) return;
    int side = (n >= NN);
    int nl = n - side * NN;
    const float* x = side ? xd : xp;
    const int* batch = side ? bd : bp;
    float xa = x[nl * FIN + lane];
    float xb = x[nl * FIN + 32 + lane];
    float acc0 = gb1[lane];
    float acc1 = gb1[lane + 32];
#pragma unroll
    for (int k = 0; k < FIN; k++) {
        float xk = __shfl_sync(0xffffffffu, (k < 32) ? xa : xb, k & 31);
        acc0 += xk * gW1[k * FIN + lane];
        acc1 += xk * gW1[k * FIN + lane + 32];
    }
    float h = fmaxf(acc0, 0.f) * gW2[lane] + fmaxf(acc1, 0.f) * gW2[lane + 32];
#pragma unroll
    for (int o = 16; o > 0; o >>= 1) h += __shfl_down_sync(0xffffffffu, h, o);
    if (lane == 0) {
        float e = expf(h + gb2[0]);        // gates tiny: no max-shift needed
        g_gate[n] = e;
        int b = batch[nl];
        atomicAdd(&g_z.gden[side][b], e);
        atomicAdd(&g_z.cnt[side][b], 1);
    }
}

__global__ void k_attpool(const float* __restrict__ xp, const float* __restrict__ xd,
                          const int* __restrict__ bp, const int* __restrict__ bd) {
    int idx = blockIdx.x * blockDim.x + threadIdx.x;     // NN2 * 16
    if (idx >= NN2 * (FIN / 4)) return;
    int n = idx >> 4, j = idx & 15;
    int side = (n >= NN);
    int nl = n - side * NN;
    int b = side ? bd[nl] : bp[nl];
    float alpha = g_gate[n] / g_z.gden[side][b];
    const float4* x4 = side ? (const float4*)xd : (const float4*)xp;
    float4 v = __ldg(&x4[nl * (FIN / 4) + j]);
    v.x *= alpha; v.y *= alpha; v.z *= alpha; v.w *= alpha;
    red4(&g_z.att[side][b * FIN + j * 4], v);
}

// ---------------- fp16 CSR gather (one side) -> fp16 agg -----------------------
__global__ void k_gatherh(const int4* __restrict__ f16, int K8, int side) {
    int idx = blockIdx.x * blockDim.x + threadIdx.x;     // NN * K8
    if (idx >= NN * K8) return;
    int nl = idx / K8, j = idx - nl * K8;
    int base = side * NN;
    int n = base + nl;
    float dv = g_dinv[n];
    float acc[8] = {0.f, 0.f, 0.f, 0.f, 0.f, 0.f, 0.f, 0.f};
    fma8(__ldg(&f16[(size_t)n * K8 + j]), dv * dv, acc);
    int p = __ldg(&g_coff[n]);
    int end = __ldg(&g_coff[n + 1]);
    for (; p + 3 < end; p += 4) {
        int2 e0 = __ldg(&g_edge[p]);
        int2 e1 = __ldg(&g_edge[p + 1]);
        int2 e2 = __ldg(&g_edge[p + 2]);
        int2 e3 = __ldg(&g_edge[p + 3]);
        int4 a0 = __ldg(&f16[(size_t)(base + e0.x) * K8 + j]);
        int4 a1 = __ldg(&f16[(size_t)(base + e1.x) * K8 + j]);
        int4 a2 = __ldg(&f16[(size_t)(base + e2.x) * K8 + j]);
        int4 a3 = __ldg(&f16[(size_t)(base + e3.x) * K8 + j]);
        fma8(a0, __int_as_float(e0.y), acc);
        fma8(a1, __int_as_float(e1.y), acc);
        fma8(a2, __int_as_float(e2.y), acc);
        fma8(a3, __int_as_float(e3.y), acc);
    }
    for (; p < end; p++) {
        int2 e0 = __ldg(&g_edge[p]);
        fma8(__ldg(&f16[(size_t)(base + e0.x) * K8 + j]), __int_as_float(e0.y), acc);
    }
    __half2 h0 = __floats2half2_rn(acc[0], acc[1]);
    __half2 h1 = __floats2half2_rn(acc[2], acc[3]);
    __half2 h2 = __floats2half2_rn(acc[4], acc[5]);
    __half2 h3 = __floats2half2_rn(acc[6], acc[7]);
    int4 o;
    o.x = *(int*)&h0; o.y = *(int*)&h1; o.z = *(int*)&h2; o.w = *(int*)&h3;
    ((int4*)g_aggh)[(size_t)n * K8 + j] = o;
}

// ---------------- HMMA GEMM (one side): out = aggh @ W + b ----------------------
__global__ void __launch_bounds__(256) k_gemm_mma(
        int woff, const float* __restrict__ bias,
        int K, int reluOut, int fusePool,
        const int* __restrict__ batch, int side) {
    extern __shared__ __half sm[];
    const int KS = K + 8;
    __half* As  = sm;                     // 128 x KS
    __half* Bhi = As + 128 * KS;          // 96 x KS  ([n][k])
    __half* Blo = Bhi + 96 * KS;
    const int rowBase = blockIdx.x * 128;
    const int tid = threadIdx.x;
    const int K8 = K >> 3;

    // copy preconverted weights (int4 = 8 halves)
    const int4* Wh4 = (const int4*)(g_whi + woff + side * (HD * K));
    const int4* Wl4 = (const int4*)(g_wlo + woff + side * (HD * K));
    for (int i = tid; i < HD * K8; i += 256) {
        int r = i / K8, j = i - r * K8;
        *(int4*)&Bhi[r * KS + j * 8] = __ldg(&Wh4[i]);
        *(int4*)&Blo[r * KS + j * 8] = __ldg(&Wl4[i]);
    }
    const int4* Ah = (const int4*)g_aggh;
    for (int i = tid; i < 128 * K8; i += 256) {
        int r = i / K8, j = i - r * K8;
        int row = rowBase + r;
        int4 v = make_int4(0, 0, 0, 0);
        if (row < NN) v = __ldg(&Ah[(size_t)(side * NN + row) * K8 + j]);
        *(int4*)&As[r * KS + j * 8] = v;
    }
    __syncthreads();

    const int warp = tid >> 5;
    const int lane = tid & 31;
    const int g = lane >> 2;
    const int tg = lane & 3;
    const int warpRow = warp * 16;

    float c[12][4];
#pragma unroll
    for (int nt = 0; nt < 12; nt++)
#pragma unroll
        for (int q = 0; q < 4; q++) c[nt][q] = 0.f;

    const int nk = K >> 4;
    for (int ks = 0; ks < nk; ks++) {
        unsigned a[4];
        const __half* arow0 = &As[(warpRow + g) * KS + ks * 16 + tg * 2];
        const __half* arow1 = arow0 + 8 * KS;
        a[0] = *(const unsigned*)arow0;
        a[1] = *(const unsigned*)arow1;
        a[2] = *(const unsigned*)(arow0 + 8);
        a[3] = *(const unsigned*)(arow1 + 8);
#pragma unroll
        for (int nt = 0; nt < 12; nt++) {
            const __half* brow = &Bhi[(nt * 8 + g) * KS + ks * 16 + tg * 2];
            unsigned b0 = *(const unsigned*)brow;
            unsigned b1 = *(const unsigned*)(brow + 8);
            mma16816(c[nt], a, b0, b1);
            const __half* brl = &Blo[(nt * 8 + g) * KS + ks * 16 + tg * 2];
            unsigned l0 = *(const unsigned*)brl;
            unsigned l1 = *(const unsigned*)(brl + 8);
            mma16816(c[nt], a, l0, l1);
        }
    }

    int row0 = rowBase + warpRow + g;
    int row1 = row0 + 8;
#pragma unroll
    for (int nt = 0; nt < 12; nt++) {
        int col = nt * 8 + tg * 2;
        float bx = __ldg(&bias[col]);
        float by = __ldg(&bias[col + 1]);
        float v00 = c[nt][0] + bx, v01 = c[nt][1] + by;
        float v10 = c[nt][2] + bx, v11 = c[nt][3] + by;
        if (!fusePool) {
            if (reluOut) {
                v00 = fmaxf(v00, 0.f); v01 = fmaxf(v01, 0.f);
                v10 = fmaxf(v10, 0.f); v11 = fmaxf(v11, 0.f);
            }
            if (row0 < NN) {
                __half2 h = __floats2half2_rn(v00, v01);
                *(unsigned*)&g_hh[(size_t)(side * NN + row0) * HD + col] = *(unsigned*)&h;
            }
            if (row1 < NN) {
                __half2 h = __floats2half2_rn(v10, v11);
                *(unsigned*)&g_hh[(size_t)(side * NN + row1) * HD + col] = *(unsigned*)&h;
            }
        } else {
            if (row0 < NN) red2(&g_z.pool[side][batch[row0] * HD + col], v00, v01);
            if (row1 < NN) red2(&g_z.pool[side][batch[row1] * HD + col], v10, v11);
        }
    }
}

// ---------------- final MLP ---------------------------------------------------
__global__ void k_final(const float* __restrict__ lW0, const float* __restrict__ lb0,
                        const float* __restrict__ lW1, const float* __restrict__ lb1,
                        float* __restrict__ out) {
    int g = blockIdx.x;
    int j = threadIdx.x;                                 // 96 threads
    __shared__ float cat[2 * HD + 2 * FIN];              // 320
    __shared__ float red[HD];
    for (int i = j; i < 2 * HD + 2 * FIN; i += HD) {
        float v;
        if (i < HD)            v = g_z.pool[0][g * HD + i] / fmaxf((float)g_z.cnt[0][g], 1.f);
        else if (i < 2 * HD)   v = g_z.pool[1][g * HD + (i - HD)] / fmaxf((float)g_z.cnt[1][g], 1.f);
        else if (i < 2 * HD + FIN) v = g_z.att[0][g * FIN + (i - 2 * HD)];
        else                   v = g_z.att[1][g * FIN + (i - 2 * HD - FIN)];
        cat[i] = v;
    }
    __syncthreads();
    float acc = lb0[j];
#pragma unroll 8
    for (int i = 0; i < 2 * HD + 2 * FIN; i++)
        acc += cat[i] * lW0[i * HD + j];
    red[j] = fmaxf(acc, 0.f) * lW1[j];
    __syncthreads();
    if (j == 0) {
        float s = lb1[0];
        for (int t = 0; t < HD; t++) s += red[t];
        out[g] = s;
    }
}

// ---------------- host launcher ----------------------------------------------
extern "C" void kernel_launch(void* const* d_in, const int* in_sizes, int n_in,
                              void* d_out, int out_size) {
    const float* xp  = (const float*)d_in[0];
    const float* xd  = (const float*)d_in[1];
    const int*   eip = (const int*)d_in[4];
    const int*   eid = (const int*)d_in[5];
    const int*   bp  = (const int*)d_in[6];
    const int*   bd  = (const int*)d_in[7];
    const float* Wp0 = (const float*)d_in[8],  *bp0 = (const float*)d_in[9];
    const float* Wp1 = (const float*)d_in[10], *bp1 = (const float*)d_in[11];
    const float* Wp2 = (const float*)d_in[12], *bp2 = (const float*)d_in[13];
    const float* Wd0 = (const float*)d_in[14], *bd0 = (const float*)d_in[15];
    const float* Wd1 = (const float*)d_in[16], *bd1 = (const float*)d_in[17];
    const float* Wd2 = (const float*)d_in[18], *bd2 = (const float*)d_in[19];
    const float* gW1 = (const float*)d_in[20], *gb1 = (const float*)d_in[21];
    const float* gW2 = (const float*)d_in[22], *gb2 = (const float*)d_in[23];
    const float* lW0 = (const float*)d_in[24], *lb0 = (const float*)d_in[25];
    const float* lW1 = (const float*)d_in[26], *lb1 = (const float*)d_in[27];

    const int TB = 256;
    const int GB_E2 = (NE2 + TB - 1) / TB;
    const int GB_C16 = (NN2 * 16 + TB - 1) / TB;
    const int GB_S8  = (NN * 8 + TB - 1) / TB;       // per-side gather K8=8
    const int GB_S12 = (NN * 12 + TB - 1) / TB;      // per-side gather K8=12
    const int GEMM_GRID = 391;                       // per-side tiles
    const int SMEM96 = (128 + 96 + 96) * (96 + 8) * 2;   // 66560 B
    const int SMEM64 = (128 + 96 + 96) * (64 + 8) * 2;   // 46080 B

    static cudaStream_t sB = nullptr, sC = nullptr;
    static cudaEvent_t ev1 = nullptr, evT = nullptr, evB = nullptr,
                       evCSR = nullptr, evC = nullptr;
    static int inited = 0;
    if (!inited) {
        cudaFuncSetAttribute(k_gemm_mma, cudaFuncAttributeMaxDynamicSharedMemorySize, SMEM96);
        cudaStreamCreateWithFlags(&sB, cudaStreamNonBlocking);
        cudaStreamCreateWithFlags(&sC, cudaStreamNonBlocking);
        cudaEventCreateWithFlags(&ev1, cudaEventDisableTiming);
        cudaEventCreateWithFlags(&evT, cudaEventDisableTiming);
        cudaEventCreateWithFlags(&evB, cudaEventDisableTiming);
        cudaEventCreateWithFlags(&evCSR, cudaEventDisableTiming);
        cudaEventCreateWithFlags(&evC, cudaEventDisableTiming);
        inited = 1;
    }

    void* xh_dev = nullptr;  cudaGetSymbolAddress(&xh_dev, g_xh);
    void* hh_dev = nullptr;  cudaGetSymbolAddress(&hh_dev, g_hh);
    void* deg_dev = nullptr; cudaGetSymbolAddress(&deg_dev, g_deg);
    void* z_dev = nullptr;   cudaGetSymbolAddress(&z_dev, g_z);

    // ---- fork ----
    cudaEventRecord(ev1, 0);
    cudaStreamWaitEvent(sB, ev1, 0);
    cudaStreamWaitEvent(sC, ev1, 0);

    // stream B: zero-init, weight prep + tohalf, then gate+attpool
    cudaMemsetAsync(z_dev, 0, sizeof(ZeroBlk), sB);
    k_prepw<<<(WTOT + TB - 1) / TB, TB, 0, sB>>>(Wp0, Wd0, Wp1, Wd1, Wp2, Wd2);
    k_tohalf<<<GB_C16, TB, 0, sB>>>((const float4*)xp, (const float4*)xd);
    cudaEventRecord(evT, sB);                 // side chains need prepw+tohalf
    k_gate<<<(NN2 + 7) / 8, 256, 0, sB>>>(xp, xd, bp, bd, gW1, gb1, gW2, gb2);
    k_attpool<<<GB_C16, TB, 0, sB>>>(xp, xd, bp, bd);
    cudaEventRecord(evB, sB);                 // k_final needs this

    // stream A (default): CSR build (both sides)
    cudaMemsetAsync(deg_dev, 0, NN2 * sizeof(int), 0);
    k_deg<<<GB_E2, TB>>>(eip, eid);
    k_scan1<<<NSCB2, SCB>>>();
    k_scan3<<<NSCB2, SCB>>>();
    k_csrfill<<<GB_E2, TB>>>(eip, eid);
    cudaEventRecord(evCSR, 0);

    // side-p chain on stream A (needs tohalf/prepw from B)
    cudaStreamWaitEvent(0, evT, 0);
    k_gatherh<<<GB_S8, TB>>>((const int4*)xh_dev, 8, 0);
    k_gemm_mma<<<GEMM_GRID, 256, SMEM64>>>(WOFF_L0, bp0, 64, 1, 0, bp, 0);
    k_gatherh<<<GB_S12, TB>>>((const int4*)hh_dev, 12, 0);
    k_gemm_mma<<<GEMM_GRID, 256, SMEM96>>>(WOFF_L1, bp1, 96, 1, 0, bp, 0);
    k_gatherh<<<GB_S12, TB>>>((const int4*)hh_dev, 12, 0);
    k_gemm_mma<<<GEMM_GRID, 256, SMEM96>>>(WOFF_L2, bp2, 96, 0, 1, bp, 0);

    // side-d chain on stream C (needs CSR from A + tohalf/prepw from B)
    cudaStreamWaitEvent(sC, evCSR, 0);
    cudaStreamWaitEvent(sC, evT, 0);
    k_gatherh<<<GB_S8, TB, 0, sC>>>((const int4*)xh_dev, 8, 1);
    k_gemm_mma<<<GEMM_GRID, 256, SMEM64, sC>>>(WOFF_L0, bd0, 64, 1, 0, bd, 1);
    k_gatherh<<<GB_S12, TB, 0, sC>>>((const int4*)hh_dev, 12, 1);
    k_gemm_mma<<<GEMM_GRID, 256, SMEM96, sC>>>(WOFF_L1, bd1, 96, 1, 0, bd, 1);
    k_gatherh<<<GB_S12, TB, 0, sC>>>((const int4*)hh_dev, 12, 1);
    k_gemm_mma<<<GEMM_GRID, 256, SMEM96, sC>>>(WOFF_L2, bd2, 96, 0, 1, bd, 1);
    cudaEventRecord(evC, sC);

    // join: k_final needs side-p (stream A order), side-d (evC), attpool (evB)
    cudaStreamWaitEvent(0, evC, 0);
    cudaStreamWaitEvent(0, evB, 0);
    k_final<<<NG, HD>>>(lW0, lb0, lW1, lb1, (float*)d_out);
}

// round 15
// speedup vs baseline: 1.7784x; 1.0199x over previous
#include <cuda_runtime.h>
#include <cuda_fp16.h>
#include <math.h>

#define NN 50000
#define NN2 100000
#define NE 800000
#define NE2 1600000
#define FIN 64
#define HD 96
#define NG 256
#define SCB 512
#define NSCB2 ((NN2 + SCB - 1) / SCB)   // 196

// weight pack offsets (halves): [L0s0,L0s1, L1s0,L1s1, L2s0,L2s1], transposed [n][k]
#define WOFF_L0 0
#define WOFF_L1 12288            // 2*64*96
#define WOFF_L2 30720            // + 2*96*96
#define WTOT    49152            // + 2*96*96

// ---------------- scratch (device globals; no runtime allocation) -----------
__device__ __align__(16) __half g_hh[NN2 * HD];   // layer outputs, fp16
__device__ __align__(16) __half g_xh[NN2 * FIN];  // input features, fp16
__device__ __align__(16) __half g_aggh[NN2 * HD]; // gather outputs, fp16
__device__ __align__(16) __half g_whi[WTOT];      // weights hi, fp16, [n][k]
__device__ __align__(16) __half g_wlo[WTOT];      // weights lo (residual)
__device__ float g_dinv[NN2];
__device__ int   g_deg[NN2];
__device__ int   g_coff[NN2 + 1];
__device__ int   g_cur[NN2];
__device__ __align__(8) int2 g_edge[NE2];         // (local src, norm-bits)
__device__ int   g_bsum[256];
__device__ float g_gate[NN2];

// zero-initialized-per-iteration block (single memset)
struct __align__(16) ZeroBlk {
    float gden[2][NG];
    int   cnt[2][NG];
    float att[2][NG * FIN];
    float pool[2][NG * HD];
};
__device__ ZeroBlk g_z;

// ---------------- helpers ----------------------------------------------------
__device__ __forceinline__ void red4(float* p, float4 v) {
    asm volatile("red.global.add.v4.f32 [%0], {%1,%2,%3,%4};"
                 :: "l"(p), "f"(v.x), "f"(v.y), "f"(v.z), "f"(v.w) : "memory");
}
__device__ __forceinline__ void red2(float* p, float a, float b) {
    asm volatile("red.global.add.v2.f32 [%0], {%1,%2};"
                 :: "l"(p), "f"(a), "f"(b) : "memory");
}

__device__ __forceinline__ void mma16816(float* c, const unsigned* a, unsigned b0, unsigned b1) {
    asm volatile(
        "mma.sync.aligned.m16n8k16.row.col.f32.f16.f16.f32 "
        "{%0,%1,%2,%3}, {%4,%5,%6,%7}, {%8,%9}, {%0,%1,%2,%3};"
        : "+f"(c[0]), "+f"(c[1]), "+f"(c[2]), "+f"(c[3])
        : "r"(a[0]), "r"(a[1]), "r"(a[2]), "r"(a[3]), "r"(b0), "r"(b1));
}

// acc[0..3] (half2) += w2 * (8 halves in raw) — pure HFMA2, no conversions
__device__ __forceinline__ void fma8h(int4 raw, __half2 w2, __half2* acc) {
    __half2* h = reinterpret_cast<__half2*>(&raw);
    acc[0] = __hfma2(h[0], w2, acc[0]);
    acc[1] = __hfma2(h[1], w2, acc[1]);
    acc[2] = __hfma2(h[2], w2, acc[2]);
    acc[3] = __hfma2(h[3], w2, acc[3]);
}

// ---------------- weight preconversion: fp32 [k][n] -> hi/lo fp16 [n][k] -------
__global__ void k_prepw(const float* __restrict__ Wp0, const float* __restrict__ Wd0,
                        const float* __restrict__ Wp1, const float* __restrict__ Wd1,
                        const float* __restrict__ Wp2, const float* __restrict__ Wd2) {
    int idx = blockIdx.x * blockDim.x + threadIdx.x;
    if (idx >= WTOT) return;
    const float* W;
    int K, base, e;
    if (idx < WOFF_L1) {
        int t = idx - WOFF_L0;  K = 64;
        int side = t / 6144;    e = t - side * 6144;
        W = side ? Wd0 : Wp0;   base = WOFF_L0 + side * 6144;
    } else if (idx < WOFF_L2) {
        int t = idx - WOFF_L1;  K = 96;
        int side = t / 9216;    e = t - side * 9216;
        W = side ? Wd1 : Wp1;   base = WOFF_L1 + side * 9216;
    } else {
        int t = idx - WOFF_L2;  K = 96;
        int side = t / 9216;    e = t - side * 9216;
        W = side ? Wd2 : Wp2;   base = WOFF_L2 + side * 9216;
    }
    int k = e / HD, n = e - k * HD;
    float w = __ldg(&W[k * HD + n]);
    __half hi = __float2half_rn(w);
    __half lo = __float2half_rn(w - __half2float(hi));
    g_whi[base + n * K + k] = hi;
    g_wlo[base + n * K + k] = lo;
}

// ---------------- input conversion ---------------------------------------------
__global__ void k_tohalf(const float4* __restrict__ xp, const float4* __restrict__ xd) {
    int idx = blockIdx.x * blockDim.x + threadIdx.x;      // NN2 * 16
    if (idx >= NN2 * 16) return;
    int n = idx >> 4;
    int side = (n >= NN);
    int nl = n - side * NN;
    float4 v = __ldg(&(side ? xd : xp)[nl * 16 + (idx & 15)]);
    __half2 h0 = __floats2half2_rn(v.x, v.y);
    __half2 h1 = __floats2half2_rn(v.z, v.w);
    uint2 u;
    u.x = *(unsigned*)&h0; u.y = *(unsigned*)&h1;
    ((uint2*)g_xh)[idx] = u;
}

__global__ void k_deg(const int* __restrict__ eip, const int* __restrict__ eid) {
    int e = blockIdx.x * blockDim.x + threadIdx.x;
    if (e >= NE2) return;
    int side = (e >= NE);
    int el = e - side * NE;
    const int* ei = side ? eid : eip;
    atomicAdd(&g_deg[side * NN + ei[NE + el]], 1);
}

// ---------------- CSR build ----------------------------------------------------
__global__ void k_scan1() {
    __shared__ int s[SCB];
    int i = blockIdx.x * SCB + threadIdx.x;
    s[threadIdx.x] = (i < NN2) ? g_deg[i] : 0;
    __syncthreads();
    for (int o = SCB / 2; o > 0; o >>= 1) {
        if (threadIdx.x < o) s[threadIdx.x] += s[threadIdx.x + o];
        __syncthreads();
    }
    if (threadIdx.x == 0) g_bsum[blockIdx.x] = s[0];
}

__global__ void k_scan3() {
    __shared__ int sb[SCB];
    int t = threadIdx.x;
    sb[t] = (t < blockIdx.x) ? g_bsum[t] : 0;
    __syncthreads();
    for (int o = SCB / 2; o > 0; o >>= 1) {
        if (t < o) sb[t] += sb[t + o];
        __syncthreads();
    }
    int boff = sb[0];
    __syncthreads();
    int i = blockIdx.x * SCB + t;
    int v = (i < NN2) ? g_deg[i] : 0;
    sb[t] = v;
    __syncthreads();
    for (int o = 1; o < SCB; o <<= 1) {
        int a = (t >= o) ? sb[t - o] : 0;
        __syncthreads();
        sb[t] += a;
        __syncthreads();
    }
    if (i < NN2) {
        int off = boff + sb[t] - v;                 // exclusive
        g_coff[i] = off;
        g_cur[i] = off;
        g_dinv[i] = rsqrtf((float)v + 1.0f);
    }
    if (blockIdx.x == NSCB2 - 1 && t == SCB - 1) g_coff[NN2] = boff + sb[t];
}

__global__ void k_csrfill(const int* __restrict__ eip, const int* __restrict__ eid) {
    int e = blockIdx.x * blockDim.x + threadIdx.x;
    if (e >= NE2) return;
    int side = (e >= NE);
    int el = e - side * NE;
    const int* ei = side ? eid : eip;
    int s = ei[el], d = ei[NE + el];
    int base = side * NN;
    float norm = g_dinv[base + s] * g_dinv[base + d];
    int slot = atomicAdd(&g_cur[base + d], 1);
    g_edge[slot] = make_int2(s, __float_as_int(norm));
}

// ---------------- attention gate (both sides) ----------------------------------
__global__ void k_gate(const float* __restrict__ xp, const float* __restrict__ xd,
                       const int* __restrict__ bp, const int* __restrict__ bd,
                       const float* __restrict__ gW1, const float* __restrict__ gb1,
                       const float* __restrict__ gW2, const float* __restrict__ gb2) {
    int lane = threadIdx.x & 31;
    int n = blockIdx.x * (blockDim.x >> 5) + (threadIdx.x >> 5);
    if (n >= NN2) return;
    int side = (n >= NN);
    int nl = n - side * NN;
    const float* x = side ? xd : xp;
    const int* batch = side ? bd : bp;
    float xa = x[nl * FIN + lane];
    float xb = x[nl * FIN + 32 + lane];
    float acc0 = gb1[lane];
    float acc1 = gb1[lane + 32];
#pragma unroll
    for (int k = 0; k < FIN; k++) {
        float xk = __shfl_sync(0xffffffffu, (k < 32) ? xa : xb, k & 31);
        acc0 += xk * gW1[k * FIN + lane];
        acc1 += xk * gW1[k * FIN + lane + 32];
    }
    float h = fmaxf(acc0, 0.f) * gW2[lane] + fmaxf(acc1, 0.f) * gW2[lane + 32];
#pragma unroll
    for (int o = 16; o > 0; o >>= 1) h += __shfl_down_sync(0xffffffffu, h, o);
    if (lane == 0) {
        float e = expf(h + gb2[0]);        // gates tiny: no max-shift needed
        g_gate[n] = e;
        int b = batch[nl];
        atomicAdd(&g_z.gden[side][b], e);
        atomicAdd(&g_z.cnt[side][b], 1);
    }
}

__global__ void k_attpool(const float* __restrict__ xp, const float* __restrict__ xd,
                          const int* __restrict__ bp, const int* __restrict__ bd) {
    int idx = blockIdx.x * blockDim.x + threadIdx.x;     // NN2 * 16
    if (idx >= NN2 * (FIN / 4)) return;
    int n = idx >> 4, j = idx & 15;
    int side = (n >= NN);
    int nl = n - side * NN;
    int b = side ? bd[nl] : bp[nl];
    float alpha = g_gate[n] / g_z.gden[side][b];
    const float4* x4 = side ? (const float4*)xd : (const float4*)xp;
    float4 v = __ldg(&x4[nl * (FIN / 4) + j]);
    v.x *= alpha; v.y *= alpha; v.z *= alpha; v.w *= alpha;
    red4(&g_z.att[side][b * FIN + j * 4], v);
}

// ---------------- fp16 CSR gather (one side), HFMA2 accumulate ------------------
__global__ void k_gatherh(const int4* __restrict__ f16, int K8, int side) {
    int idx = blockIdx.x * blockDim.x + threadIdx.x;     // NN * K8
    if (idx >= NN * K8) return;
    int nl = idx / K8, j = idx - nl * K8;
    int base = side * NN;
    int n = base + nl;
    float dv = g_dinv[n];
    __half2 acc[4];
    {
        __half2 s2 = __float2half2_rn(dv * dv);
        int4 raw = __ldg(&f16[(size_t)n * K8 + j]);
        __half2* h = reinterpret_cast<__half2*>(&raw);
        acc[0] = __hmul2(h[0], s2);
        acc[1] = __hmul2(h[1], s2);
        acc[2] = __hmul2(h[2], s2);
        acc[3] = __hmul2(h[3], s2);
    }
    int p = __ldg(&g_coff[n]);
    int end = __ldg(&g_coff[n + 1]);
    for (; p + 3 < end; p += 4) {
        int2 e0 = __ldg(&g_edge[p]);
        int2 e1 = __ldg(&g_edge[p + 1]);
        int2 e2 = __ldg(&g_edge[p + 2]);
        int2 e3 = __ldg(&g_edge[p + 3]);
        int4 a0 = __ldg(&f16[(size_t)(base + e0.x) * K8 + j]);
        int4 a1 = __ldg(&f16[(size_t)(base + e1.x) * K8 + j]);
        int4 a2 = __ldg(&f16[(size_t)(base + e2.x) * K8 + j]);
        int4 a3 = __ldg(&f16[(size_t)(base + e3.x) * K8 + j]);
        fma8h(a0, __float2half2_rn(__int_as_float(e0.y)), acc);
        fma8h(a1, __float2half2_rn(__int_as_float(e1.y)), acc);
        fma8h(a2, __float2half2_rn(__int_as_float(e2.y)), acc);
        fma8h(a3, __float2half2_rn(__int_as_float(e3.y)), acc);
    }
    for (; p < end; p++) {
        int2 e0 = __ldg(&g_edge[p]);
        fma8h(__ldg(&f16[(size_t)(base + e0.x) * K8 + j]),
              __float2half2_rn(__int_as_float(e0.y)), acc);
    }
    int4 o;
    o.x = *(int*)&acc[0]; o.y = *(int*)&acc[1];
    o.z = *(int*)&acc[2]; o.w = *(int*)&acc[3];
    ((int4*)g_aggh)[(size_t)n * K8 + j] = o;
}

// ---------------- HMMA GEMM (one side): out = aggh @ W + b ----------------------
__global__ void __launch_bounds__(256) k_gemm_mma(
        int woff, const float* __restrict__ bias,
        int K, int reluOut, int fusePool,
        const int* __restrict__ batch, int side) {
    extern __shared__ __half sm[];
    const int KS = K + 8;
    __half* As  = sm;                     // 128 x KS
    __half* Bhi = As + 128 * KS;          // 96 x KS  ([n][k])
    __half* Blo = Bhi + 96 * KS;
    const int rowBase = blockIdx.x * 128;
    const int tid = threadIdx.x;
    const int K8 = K >> 3;

    // copy preconverted weights (int4 = 8 halves)
    const int4* Wh4 = (const int4*)(g_whi + woff + side * (HD * K));
    const int4* Wl4 = (const int4*)(g_wlo + woff + side * (HD * K));
    for (int i = tid; i < HD * K8; i += 256) {
        int r = i / K8, j = i - r * K8;
        *(int4*)&Bhi[r * KS + j * 8] = __ldg(&Wh4[i]);
        *(int4*)&Blo[r * KS + j * 8] = __ldg(&Wl4[i]);
    }
    const int4* Ah = (const int4*)g_aggh;
    for (int i = tid; i < 128 * K8; i += 256) {
        int r = i / K8, j = i - r * K8;
        int row = rowBase + r;
        int4 v = make_int4(0, 0, 0, 0);
        if (row < NN) v = __ldg(&Ah[(size_t)(side * NN + row) * K8 + j]);
        *(int4*)&As[r * KS + j * 8] = v;
    }
    __syncthreads();

    const int warp = tid >> 5;
    const int lane = tid & 31;
    const int g = lane >> 2;
    const int tg = lane & 3;
    const int warpRow = warp * 16;

    float c[12][4];
#pragma unroll
    for (int nt = 0; nt < 12; nt++)
#pragma unroll
        for (int q = 0; q < 4; q++) c[nt][q] = 0.f;

    const int nk = K >> 4;
    for (int ks = 0; ks < nk; ks++) {
        unsigned a[4];
        const __half* arow0 = &As[(warpRow + g) * KS + ks * 16 + tg * 2];
        const __half* arow1 = arow0 + 8 * KS;
        a[0] = *(const unsigned*)arow0;
        a[1] = *(const unsigned*)arow1;
        a[2] = *(const unsigned*)(arow0 + 8);
        a[3] = *(const unsigned*)(arow1 + 8);
#pragma unroll
        for (int nt = 0; nt < 12; nt++) {
            const __half* brow = &Bhi[(nt * 8 + g) * KS + ks * 16 + tg * 2];
            unsigned b0 = *(const unsigned*)brow;
            unsigned b1 = *(const unsigned*)(brow + 8);
            mma16816(c[nt], a, b0, b1);
            const __half* brl = &Blo[(nt * 8 + g) * KS + ks * 16 + tg * 2];
            unsigned l0 = *(const unsigned*)brl;
            unsigned l1 = *(const unsigned*)(brl + 8);
            mma16816(c[nt], a, l0, l1);
        }
    }

    int row0 = rowBase + warpRow + g;
    int row1 = row0 + 8;
#pragma unroll
    for (int nt = 0; nt < 12; nt++) {
        int col = nt * 8 + tg * 2;
        float bx = __ldg(&bias[col]);
        float by = __ldg(&bias[col + 1]);
        float v00 = c[nt][0] + bx, v01 = c[nt][1] + by;
        float v10 = c[nt][2] + bx, v11 = c[nt][3] + by;
        if (!fusePool) {
            if (reluOut) {
                v00 = fmaxf(v00, 0.f); v01 = fmaxf(v01, 0.f);
                v10 = fmaxf(v10, 0.f); v11 = fmaxf(v11, 0.f);
            }
            if (row0 < NN) {
                __half2 h = __floats2half2_rn(v00, v01);
                *(unsigned*)&g_hh[(size_t)(side * NN + row0) * HD + col] = *(unsigned*)&h;
            }
            if (row1 < NN) {
                __half2 h = __floats2half2_rn(v10, v11);
                *(unsigned*)&g_hh[(size_t)(side * NN + row1) * HD + col] = *(unsigned*)&h;
            }
        } else {
            if (row0 < NN) red2(&g_z.pool[side][batch[row0] * HD + col], v00, v01);
            if (row1 < NN) red2(&g_z.pool[side][batch[row1] * HD + col], v10, v11);
        }
    }
}

// ---------------- final MLP ---------------------------------------------------
__global__ void k_final(const float* __restrict__ lW0, const float* __restrict__ lb0,
                        const float* __restrict__ lW1, const float* __restrict__ lb1,
                        float* __restrict__ out) {
    int g = blockIdx.x;
    int j = threadIdx.x;                                 // 96 threads
    __shared__ float cat[2 * HD + 2 * FIN];              // 320
    __shared__ float red[HD];
    for (int i = j; i < 2 * HD + 2 * FIN; i += HD) {
        float v;
        if (i < HD)            v = g_z.pool[0][g * HD + i] / fmaxf((float)g_z.cnt[0][g], 1.f);
        else if (i < 2 * HD)   v = g_z.pool[1][g * HD + (i - HD)] / fmaxf((float)g_z.cnt[1][g], 1.f);
        else if (i < 2 * HD + FIN) v = g_z.att[0][g * FIN + (i - 2 * HD)];
        else                   v = g_z.att[1][g * FIN + (i - 2 * HD - FIN)];
        cat[i] = v;
    }
    __syncthreads();
    float acc = lb0[j];
#pragma unroll 8
    for (int i = 0; i < 2 * HD + 2 * FIN; i++)
        acc += cat[i] * lW0[i * HD + j];
    red[j] = fmaxf(acc, 0.f) * lW1[j];
    __syncthreads();
    if (j == 0) {
        float s = lb1[0];
        for (int t = 0; t < HD; t++) s += red[t];
        out[g] = s;
    }
}

// ---------------- host launcher ----------------------------------------------
extern "C" void kernel_launch(void* const* d_in, const int* in_sizes, int n_in,
                              void* d_out, int out_size) {
    const float* xp  = (const float*)d_in[0];
    const float* xd  = (const float*)d_in[1];
    const int*   eip = (const int*)d_in[4];
    const int*   eid = (const int*)d_in[5];
    const int*   bp  = (const int*)d_in[6];
    const int*   bd  = (const int*)d_in[7];
    const float* Wp0 = (const float*)d_in[8],  *bp0 = (const float*)d_in[9];
    const float* Wp1 = (const float*)d_in[10], *bp1 = (const float*)d_in[11];
    const float* Wp2 = (const float*)d_in[12], *bp2 = (const float*)d_in[13];
    const float* Wd0 = (const float*)d_in[14], *bd0 = (const float*)d_in[15];
    const float* Wd1 = (const float*)d_in[16], *bd1 = (const float*)d_in[17];
    const float* Wd2 = (const float*)d_in[18], *bd2 = (const float*)d_in[19];
    const float* gW1 = (const float*)d_in[20], *gb1 = (const float*)d_in[21];
    const float* gW2 = (const float*)d_in[22], *gb2 = (const float*)d_in[23];
    const float* lW0 = (const float*)d_in[24], *lb0 = (const float*)d_in[25];
    const float* lW1 = (const float*)d_in[26], *lb1 = (const float*)d_in[27];

    const int TB = 256;
    const int GB_E2 = (NE2 + TB - 1) / TB;
    const int GB_C16 = (NN2 * 16 + TB - 1) / TB;
    const int GB_S8  = (NN * 8 + TB - 1) / TB;       // per-side gather K8=8
    const int GB_S12 = (NN * 12 + TB - 1) / TB;      // per-side gather K8=12
    const int GEMM_GRID = 391;                       // per-side tiles
    const int SMEM96 = (128 + 96 + 96) * (96 + 8) * 2;   // 66560 B
    const int SMEM64 = (128 + 96 + 96) * (64 + 8) * 2;   // 46080 B

    static cudaStream_t sB = nullptr, sC = nullptr;
    static cudaEvent_t ev1 = nullptr, evT = nullptr, evB = nullptr,
                       evCSR = nullptr, evC = nullptr;
    static int inited = 0;
    if (!inited) {
        cudaFuncSetAttribute(k_gemm_mma, cudaFuncAttributeMaxDynamicSharedMemorySize, SMEM96);
        cudaStreamCreateWithFlags(&sB, cudaStreamNonBlocking);
        cudaStreamCreateWithFlags(&sC, cudaStreamNonBlocking);
        cudaEventCreateWithFlags(&ev1, cudaEventDisableTiming);
        cudaEventCreateWithFlags(&evT, cudaEventDisableTiming);
        cudaEventCreateWithFlags(&evB, cudaEventDisableTiming);
        cudaEventCreateWithFlags(&evCSR, cudaEventDisableTiming);
        cudaEventCreateWithFlags(&evC, cudaEventDisableTiming);
        inited = 1;
    }

    void* xh_dev = nullptr;  cudaGetSymbolAddress(&xh_dev, g_xh);
    void* hh_dev = nullptr;  cudaGetSymbolAddress(&hh_dev, g_hh);
    void* deg_dev = nullptr; cudaGetSymbolAddress(&deg_dev, g_deg);
    void* z_dev = nullptr;   cudaGetSymbolAddress(&z_dev, g_z);

    // ---- fork ----
    cudaEventRecord(ev1, 0);
    cudaStreamWaitEvent(sB, ev1, 0);
    cudaStreamWaitEvent(sC, ev1, 0);

    // stream B: zero-init, weight prep + tohalf, then gate+attpool
    cudaMemsetAsync(z_dev, 0, sizeof(ZeroBlk), sB);
    k_prepw<<<(WTOT + TB - 1) / TB, TB, 0, sB>>>(Wp0, Wd0, Wp1, Wd1, Wp2, Wd2);
    k_tohalf<<<GB_C16, TB, 0, sB>>>((const float4*)xp, (const float4*)xd);
    cudaEventRecord(evT, sB);                 // side chains need prepw+tohalf
    k_gate<<<(NN2 + 7) / 8, 256, 0, sB>>>(xp, xd, bp, bd, gW1, gb1, gW2, gb2);
    k_attpool<<<GB_C16, TB, 0, sB>>>(xp, xd, bp, bd);
    cudaEventRecord(evB, sB);                 // k_final needs this

    // stream A (default): CSR build (both sides)
    cudaMemsetAsync(deg_dev, 0, NN2 * sizeof(int), 0);
    k_deg<<<GB_E2, TB>>>(eip, eid);
    k_scan1<<<NSCB2, SCB>>>();
    k_scan3<<<NSCB2, SCB>>>();
    k_csrfill<<<GB_E2, TB>>>(eip, eid);
    cudaEventRecord(evCSR, 0);

    // side-p chain on stream A (needs tohalf/prepw from B)
    cudaStreamWaitEvent(0, evT, 0);
    k_gatherh<<<GB_S8, TB>>>((const int4*)xh_dev, 8, 0);
    k_gemm_mma<<<GEMM_GRID, 256, SMEM64>>>(WOFF_L0, bp0, 64, 1, 0, bp, 0);
    k_gatherh<<<GB_S12, TB>>>((const int4*)hh_dev, 12, 0);
    k_gemm_mma<<<GEMM_GRID, 256, SMEM96>>>(WOFF_L1, bp1, 96, 1, 0, bp, 0);
    k_gatherh<<<GB_S12, TB>>>((const int4*)hh_dev, 12, 0);
    k_gemm_mma<<<GEMM_GRID, 256, SMEM96>>>(WOFF_L2, bp2, 96, 0, 1, bp, 0);

    // side-d chain on stream C (needs CSR from A + tohalf/prepw from B)
    cudaStreamWaitEvent(sC, evCSR, 0);
    cudaStreamWaitEvent(sC, evT, 0);
    k_gatherh<<<GB_S8, TB, 0, sC>>>((const int4*)xh_dev, 8, 1);
    k_gemm_mma<<<GEMM_GRID, 256, SMEM64, sC>>>(WOFF_L0, bd0, 64, 1, 0, bd, 1);
    k_gatherh<<<GB_S12, TB, 0, sC>>>((const int4*)hh_dev, 12, 1);
    k_gemm_mma<<<GEMM_GRID, 256, SMEM96, sC>>>(WOFF_L1, bd1, 96, 1, 0, bd, 1);
    k_gatherh<<<GB_S12, TB, 0, sC>>>((const int4*)hh_dev, 12, 1);
    k_gemm_mma<<<GEMM_GRID, 256, SMEM96, sC>>>(WOFF_L2, bd2, 96, 0, 1, bd, 1);
    cudaEventRecord(evC, sC);

    // join: k_final needs side-p (stream A order), side-d (evC), attpool (evB)
    cudaStreamWaitEvent(0, evC, 0);
    cudaStreamWaitEvent(0, evB, 0);
    k_final<<<NG, HD>>>(lW0, lb0, lW1, lb1, (float*)d_out);
}